// round 4
// baseline (speedup 1.0000x reference)
#include <cuda_runtime.h>
#include <math.h>

#define Bsz  4
#define Ssz  2048
#define Dsz  1024
#define Hsz  16
#define HDsz 64
#define Msz  (Bsz * Ssz)   // 8192

// Scratch (device globals: allocation-free rule)
__device__ float g_Q[Msz * Dsz];    // [B,H,S,hd]
__device__ float g_K[Msz * Dsz];    // [B,H,S,hd]
__device__ float g_V[Msz * Dsz];    // [B,H,S,hd]
__device__ float g_AO[Msz * Dsz];   // [B,S,H*hd] = [M,1024]

// ---------------------------------------------------------------------------
// SGEMM mainloop: C[128,128] tile of A[M,1024] * W[N,1024]^T  (NT, K-major both)
// 256 threads, 8x8 per thread, BK=16, single smem buffer + LDG register prefetch
// ---------------------------------------------------------------------------
__device__ __forceinline__ void sgemm_main(const float* __restrict__ A,
                                           const float* __restrict__ W,
                                           float (*acc)[8],
                                           float* As, float* Bs,
                                           int bm, int bn)
{
    const int t = threadIdx.x;
    const int rg = (t >> 4) << 3;   // 0..120 step 8
    const int cg = (t & 15) << 3;

    float4 ra[2], rb[2];

    auto ldg = [&](int k0) {
#pragma unroll
        for (int i = 0; i < 2; i++) {
            int id  = t + i * 256;
            int row = id >> 2;
            int cq  = (id & 3) << 2;
            ra[i] = *(const float4*)&A[(bm + row) * 1024 + k0 + cq];
            rb[i] = *(const float4*)&W[(bn + row) * 1024 + k0 + cq];
        }
    };
    auto sts = [&]() {
#pragma unroll
        for (int i = 0; i < 2; i++) {
            int id  = t + i * 256;
            int row = id >> 2;
            int cq  = (id & 3) << 2;
            As[(cq + 0) * 128 + row] = ra[i].x;
            As[(cq + 1) * 128 + row] = ra[i].y;
            As[(cq + 2) * 128 + row] = ra[i].z;
            As[(cq + 3) * 128 + row] = ra[i].w;
            Bs[(cq + 0) * 128 + row] = rb[i].x;
            Bs[(cq + 1) * 128 + row] = rb[i].y;
            Bs[(cq + 2) * 128 + row] = rb[i].z;
            Bs[(cq + 3) * 128 + row] = rb[i].w;
        }
    };

    ldg(0);
    sts();
    __syncthreads();

#pragma unroll 1
    for (int k0 = 0; k0 < 1024; k0 += 16) {
        const bool more = (k0 + 16 < 1024);
        if (more) ldg(k0 + 16);
#pragma unroll
        for (int kk = 0; kk < 16; kk++) {
            float a[8], b[8];
            *(float4*)&a[0] = *(const float4*)&As[kk * 128 + rg];
            *(float4*)&a[4] = *(const float4*)&As[kk * 128 + rg + 4];
            *(float4*)&b[0] = *(const float4*)&Bs[kk * 128 + cg];
            *(float4*)&b[4] = *(const float4*)&Bs[kk * 128 + cg + 4];
#pragma unroll
            for (int i = 0; i < 8; i++)
#pragma unroll
                for (int j = 0; j < 8; j++)
                    acc[i][j] += a[i] * b[j];
        }
        if (more) {
            __syncthreads();
            sts();
            __syncthreads();
        }
    }
}

// ---------------------------------------------------------------------------
// QKV projection: grid (8, 64, 3).  z selects W / destination / scale.
// Epilogue scatters into [B,H,S,hd] layout; Q gets the 1/sqrt(hd) scale.
// ---------------------------------------------------------------------------
__global__ __launch_bounds__(256)
void qkv_gemm_kernel(const float* __restrict__ X,
                     const float* __restrict__ Wq,
                     const float* __restrict__ Wk,
                     const float* __restrict__ Wv)
{
    __shared__ float As[16 * 128];
    __shared__ float Bs[16 * 128];

    const int z = blockIdx.z;
    const float* W  = (z == 0) ? Wq : (z == 1) ? Wk : Wv;
    float*      Dst = (z == 0) ? g_Q : (z == 1) ? g_K : g_V;
    const float scale = (z == 0) ? 0.125f : 1.0f;

    const int bm = blockIdx.y * 128;
    const int bn = blockIdx.x * 128;

    float acc[8][8];
#pragma unroll
    for (int i = 0; i < 8; i++)
#pragma unroll
        for (int j = 0; j < 8; j++) acc[i][j] = 0.0f;

    sgemm_main(X, W, acc, As, Bs, bm, bn);

    const int rg = (threadIdx.x >> 4) << 3;
    const int cg = (threadIdx.x & 15) << 3;
    const int n0 = bn + cg;
    const int h  = n0 >> 6;
    const int d  = n0 & 63;           // d..d+7 stays inside one head (8 | 64)

#pragma unroll
    for (int i = 0; i < 8; i++) {
        int m = bm + rg + i;
        int b = m >> 11;
        int s = m & 2047;
        float* p = &Dst[(((size_t)(b * Hsz + h)) * Ssz + s) * HDsz + d];
        float4 v0, v1;
        v0.x = acc[i][0] * scale; v0.y = acc[i][1] * scale;
        v0.z = acc[i][2] * scale; v0.w = acc[i][3] * scale;
        v1.x = acc[i][4] * scale; v1.y = acc[i][5] * scale;
        v1.z = acc[i][6] * scale; v1.w = acc[i][7] * scale;
        *(float4*)p       = v0;
        *(float4*)(p + 4) = v1;
    }
}

// ---------------------------------------------------------------------------
// Output projection: C = g_AO[M,1024] * Wo[1024,1024]^T -> d_out (row-major)
// ---------------------------------------------------------------------------
__global__ __launch_bounds__(256)
void out_gemm_kernel(const float* __restrict__ Wo, float* __restrict__ Out)
{
    __shared__ float As[16 * 128];
    __shared__ float Bs[16 * 128];

    const int bm = blockIdx.y * 128;
    const int bn = blockIdx.x * 128;

    float acc[8][8];
#pragma unroll
    for (int i = 0; i < 8; i++)
#pragma unroll
        for (int j = 0; j < 8; j++) acc[i][j] = 0.0f;

    sgemm_main(g_AO, Wo, acc, As, Bs, bm, bn);

    const int rg = (threadIdx.x >> 4) << 3;
    const int cg = (threadIdx.x & 15) << 3;
#pragma unroll
    for (int i = 0; i < 8; i++) {
        int m = bm + rg + i;
        float* p = &Out[(size_t)m * 1024 + bn + cg];
        float4 v0, v1;
        v0.x = acc[i][0]; v0.y = acc[i][1]; v0.z = acc[i][2]; v0.w = acc[i][3];
        v1.x = acc[i][4]; v1.y = acc[i][5]; v1.z = acc[i][6]; v1.w = acc[i][7];
        *(float4*)p       = v0;
        *(float4*)(p + 4) = v1;
    }
}

// ---------------------------------------------------------------------------
// Flash attention (fp32, online softmax).
// grid (S/64 = 32, B*H = 64), 256 threads.
// Per CTA: 64 q rows x hd=64, streaming 32 KV blocks of 64 rows.
// Thread (rg,cg) owns a 4x4 score tile and a 4(row) x 4(d) output tile.
// Smem: Sq[d][r], Sk[d][c] (transposed, stride 68), Sv[c][d], Sp[r][c].
// ---------------------------------------------------------------------------
__global__ __launch_bounds__(256)
void attn_kernel()
{
    extern __shared__ float smem[];
    float* Sq = smem;                // 64*68
    float* Sk = Sq + 64 * 68;
    float* Sv = Sk + 64 * 68;
    float* Sp = Sv + 64 * 68;

    const int t  = threadIdx.x;
    const int qb = blockIdx.x;
    const int bh = blockIdx.y;

    const float* Qp = g_Q + (size_t)bh * (Ssz * HDsz) + qb * (64 * HDsz);
    const float* Kp = g_K + (size_t)bh * (Ssz * HDsz);
    const float* Vp = g_V + (size_t)bh * (Ssz * HDsz);

    // Q tile -> Sq transposed [d][r]
#pragma unroll
    for (int i = 0; i < 4; i++) {
        int idx = t + i * 256;
        int r   = idx >> 4;
        int dq  = (idx & 15) << 2;
        float4 v = *(const float4*)&Qp[r * 64 + dq];
        Sq[(dq + 0) * 68 + r] = v.x;
        Sq[(dq + 1) * 68 + r] = v.y;
        Sq[(dq + 2) * 68 + r] = v.z;
        Sq[(dq + 3) * 68 + r] = v.w;
    }

    float4 rk[4], rv[4];
    auto ldg_kv = [&](int kb) {
        const float* kp = Kp + kb * 64 * 64;
        const float* vp = Vp + kb * 64 * 64;
#pragma unroll
        for (int i = 0; i < 4; i++) {
            int idx = t + i * 256;
            int r   = idx >> 4;
            int dq  = (idx & 15) << 2;
            rk[i] = *(const float4*)&kp[r * 64 + dq];
            rv[i] = *(const float4*)&vp[r * 64 + dq];
        }
    };
    auto sts_kv = [&]() {
#pragma unroll
        for (int i = 0; i < 4; i++) {
            int idx = t + i * 256;
            int r   = idx >> 4;
            int dq  = (idx & 15) << 2;
            Sk[(dq + 0) * 68 + r] = rk[i].x;
            Sk[(dq + 1) * 68 + r] = rk[i].y;
            Sk[(dq + 2) * 68 + r] = rk[i].z;
            Sk[(dq + 3) * 68 + r] = rk[i].w;
            *(float4*)&Sv[r * 68 + dq] = rv[i];
        }
    };

    ldg_kv(0);
    sts_kv();
    __syncthreads();

    const int rg = t >> 4;     // 0..15 (lane bit 4 = rg parity -> 16-lane groups)
    const int cg = t & 15;
    const int r0 = rg << 2;
    const int c0 = cg << 2;

    float o[4][4];
    float mrow[4], lrow[4];
#pragma unroll
    for (int i = 0; i < 4; i++) {
        mrow[i] = -1e30f;
        lrow[i] = 0.0f;
#pragma unroll
        for (int j = 0; j < 4; j++) o[i][j] = 0.0f;
    }

    for (int kb = 0; kb < 32; kb++) {
        if (kb + 1 < 32) ldg_kv(kb + 1);

        // ---- scores: sc[i][j] = sum_d Q[r0+i][d] * K[c0+j][d]
        float sc[4][4];
#pragma unroll
        for (int i = 0; i < 4; i++)
#pragma unroll
            for (int j = 0; j < 4; j++) sc[i][j] = 0.0f;

#pragma unroll 16
        for (int d = 0; d < 64; d++) {
            float qa[4], ka[4];
            *(float4*)qa = *(const float4*)&Sq[d * 68 + r0];
            *(float4*)ka = *(const float4*)&Sk[d * 68 + c0];
#pragma unroll
            for (int i = 0; i < 4; i++)
#pragma unroll
                for (int j = 0; j < 4; j++)
                    sc[i][j] += qa[i] * ka[j];
        }

        // ---- online softmax (row stats across 16-lane group)
        float mloc[4];
#pragma unroll
        for (int i = 0; i < 4; i++)
            mloc[i] = fmaxf(fmaxf(sc[i][0], sc[i][1]), fmaxf(sc[i][2], sc[i][3]));
#pragma unroll
        for (int off = 1; off < 16; off <<= 1)
#pragma unroll
            for (int i = 0; i < 4; i++)
                mloc[i] = fmaxf(mloc[i], __shfl_xor_sync(0xffffffffu, mloc[i], off));

        float alpha[4], lloc[4];
#pragma unroll
        for (int i = 0; i < 4; i++) {
            float mn = fmaxf(mrow[i], mloc[i]);
            alpha[i] = __expf(mrow[i] - mn);
            mrow[i]  = mn;
            sc[i][0] = __expf(sc[i][0] - mn);
            sc[i][1] = __expf(sc[i][1] - mn);
            sc[i][2] = __expf(sc[i][2] - mn);
            sc[i][3] = __expf(sc[i][3] - mn);
            lloc[i]  = (sc[i][0] + sc[i][1]) + (sc[i][2] + sc[i][3]);
        }
#pragma unroll
        for (int off = 1; off < 16; off <<= 1)
#pragma unroll
            for (int i = 0; i < 4; i++)
                lloc[i] += __shfl_xor_sync(0xffffffffu, lloc[i], off);
#pragma unroll
        for (int i = 0; i < 4; i++) {
            lrow[i] = lrow[i] * alpha[i] + lloc[i];
#pragma unroll
            for (int j = 0; j < 4; j++) o[i][j] *= alpha[i];
        }

        // ---- P -> smem (consumed only within the same 16-lane group)
#pragma unroll
        for (int i = 0; i < 4; i++)
            *(float4*)&Sp[(r0 + i) * 68 + c0] =
                make_float4(sc[i][0], sc[i][1], sc[i][2], sc[i][3]);
        __syncwarp();

        // ---- O += P * V  (thread owns rows r0..r0+3, dims c0..c0+3)
#pragma unroll 4
        for (int c = 0; c < 64; c += 4) {
            float pa[4][4], va[4][4];
#pragma unroll
            for (int i = 0; i < 4; i++)
                *(float4*)pa[i] = *(const float4*)&Sp[(r0 + i) * 68 + c];
#pragma unroll
            for (int jj = 0; jj < 4; jj++)
                *(float4*)va[jj] = *(const float4*)&Sv[(c + jj) * 68 + c0];
#pragma unroll
            for (int i = 0; i < 4; i++)
#pragma unroll
                for (int jj = 0; jj < 4; jj++)
#pragma unroll
                    for (int j = 0; j < 4; j++)
                        o[i][j] += pa[i][jj] * va[jj][j];
        }

        __syncthreads();               // all reads of Sk/Sv/Sp done
        if (kb + 1 < 32) {
            sts_kv();
            __syncthreads();
        }
    }

    // ---- epilogue: normalize, write g_AO[b, s, h*64 + d]
    const int b = bh >> 4;
    const int h = bh & 15;
#pragma unroll
    for (int i = 0; i < 4; i++) {
        float inv = 1.0f / lrow[i];
        int s = qb * 64 + r0 + i;
        float* p = &g_AO[((size_t)(b * Ssz + s)) * Dsz + h * HDsz + c0];
        *(float4*)p = make_float4(o[i][0] * inv, o[i][1] * inv,
                                  o[i][2] * inv, o[i][3] * inv);
    }
}

// ---------------------------------------------------------------------------
extern "C" void kernel_launch(void* const* d_in, const int* in_sizes, int n_in,
                              void* d_out, int out_size)
{
    const float* X  = (const float*)d_in[0];
    const float* Wq = (const float*)d_in[1];
    const float* Wk = (const float*)d_in[2];
    const float* Wv = (const float*)d_in[3];
    const float* Wo = (const float*)d_in[4];
    float* Out = (float*)d_out;

    const int attn_smem = 4 * 64 * 68 * (int)sizeof(float);   // 69632 B
    cudaFuncSetAttribute(attn_kernel,
                         cudaFuncAttributeMaxDynamicSharedMemorySize, attn_smem);

    dim3 gq(8, 64, 3);
    qkv_gemm_kernel<<<gq, 256>>>(X, Wq, Wk, Wv);

    dim3 ga(32, 64);
    attn_kernel<<<ga, 256, attn_smem>>>();

    dim3 go(8, 64);
    out_gemm_kernel<<<go, 256>>>(Wo, Out);
}

// round 7
// speedup vs baseline: 1.4595x; 1.4595x over previous
#include <cuda_runtime.h>
#include <math.h>
#include <stdint.h>

#define Bsz  4
#define Ssz  2048
#define Dsz  1024
#define Hsz  16
#define HDsz 64
#define Msz  (Bsz * Ssz)   // 8192

// Scratch (device globals: allocation-free rule)
__device__ float g_Q[Msz * Dsz];    // [B,H,S,hd]
__device__ float g_K[Msz * Dsz];
__device__ float g_V[Msz * Dsz];
__device__ float g_AO[Msz * Dsz];   // [B,S,H*hd], tf32-rounded
__device__ float g_Xr[Msz * Dsz];   // X rounded to tf32 (RNA)
__device__ float g_Wq[Dsz * Dsz];
__device__ float g_Wk[Dsz * Dsz];
__device__ float g_Wv[Dsz * Dsz];
__device__ float g_Wo[Dsz * Dsz];

// ===========================================================================
// helpers
// ===========================================================================
__device__ __forceinline__ uint32_t smem_u32(const void* p) {
    uint32_t a;
    asm("{ .reg .u64 t; cvta.to.shared.u64 t, %1; cvt.u32.u64 %0, t; }"
        : "=r"(a) : "l"(p));
    return a;
}
__device__ __forceinline__ float tf32_rna(float x) {
    uint32_t u;
    asm("cvt.rna.tf32.f32 %0, %1;" : "=r"(u) : "f"(x));
    return __uint_as_float(u);
}
__device__ __forceinline__ void ldsm_x4(uint32_t& r0, uint32_t& r1,
                                        uint32_t& r2, uint32_t& r3, uint32_t a) {
    asm volatile("ldmatrix.sync.aligned.m8n8.x4.shared.b16 {%0,%1,%2,%3}, [%4];"
                 : "=r"(r0), "=r"(r1), "=r"(r2), "=r"(r3) : "r"(a));
}
__device__ __forceinline__ void mma_tf32(float* c, const uint32_t* a,
                                         const uint32_t* b) {
    asm volatile(
        "mma.sync.aligned.m16n8k8.row.col.f32.tf32.tf32.f32 "
        "{%0,%1,%2,%3}, {%4,%5,%6,%7}, {%8,%9}, {%0,%1,%2,%3};"
        : "+f"(c[0]), "+f"(c[1]), "+f"(c[2]), "+f"(c[3])
        : "r"(a[0]), "r"(a[1]), "r"(a[2]), "r"(a[3]), "r"(b[0]), "r"(b[1]));
}
__device__ __forceinline__ void cp16(uint32_t saddr, const void* gaddr) {
    asm volatile("cp.async.cg.shared.global [%0], [%1], 16;"
                 :: "r"(saddr), "l"(gaddr));
}

// ===========================================================================
// tf32 mma.sync GEMM: D[128,128] = A[bm:,1024] * W[bn:,1024]^T  (NT)
// 256 threads = 8 warps, warp tile 64x32 (warp grid 2 M x 4 N).
// BK=32, 4-stage cp.async pipeline. Smem rows padded to 36 floats (144B):
// LDSM phases hit distinct 16B banks (144 mod 128 = 16/row).
// ===========================================================================
#define BK        32
#define ROWPAD    36                        // floats per row (144B)
#define ATILE_B   (128 * ROWPAD * 4)        // 18432
#define STAGE_B   (2 * ATILE_B)             // 36864
#define NSTAGE    4
#define GSMEM     (NSTAGE * STAGE_B)        // 147456

struct CFrag { float c[4][4][4]; };         // [mt][nt][4]

__device__ __forceinline__ void tf32_gemm_main(const float* __restrict__ A,
                                               const float* __restrict__ W,
                                               int bm, int bn, char* smem,
                                               CFrag& C)
{
    const int tid  = threadIdx.x;
    const int wid  = tid >> 5;
    const int lane = tid & 31;
    const int wm   = (wid & 1) * 64;        // warp M origin (0/64)
    const int wn   = (wid >> 1) * 32;       // warp N origin (0/32/64/96)
    const uint32_t sbase = smem_u32(smem);

#pragma unroll
    for (int i = 0; i < 4; i++)
#pragma unroll
        for (int j = 0; j < 4; j++)
#pragma unroll
            for (int q = 0; q < 4; q++) C.c[i][j][q] = 0.0f;

    auto load_stage = [&](int st, int k0) {
        const uint32_t sb = sbase + st * STAGE_B;
#pragma unroll
        for (int i = 0; i < 4; i++) {
            int id  = tid + i * 256;        // 0..1023
            int row = id >> 3;              // 0..127
            int ch  = id & 7;               // 16B chunk
            uint32_t so = (uint32_t)(row * 144 + ch * 16);
            cp16(sb + so,            A + (size_t)(bm + row) * 1024 + k0 + ch * 4);
            cp16(sb + ATILE_B + so,  W + (size_t)(bn + row) * 1024 + k0 + ch * 4);
        }
        asm volatile("cp.async.commit_group;" ::: "memory");
    };

    load_stage(0, 0);
    load_stage(1, BK);
    load_stage(2, 2 * BK);

    // per-lane LDSM row/col offsets
    const int a_row = (lane & 7) + ((lane >> 3) & 1) * 8;   // + r0
    const int a_co  = (lane >> 4) * 4;                      // + k0
    const int b_row = (lane & 7) + (lane >> 4) * 8;         // + n0
    const int b_co  = ((lane >> 3) & 1) * 4;                // + k0

    for (int k = 0; k < 32; k++) {
        const int st = k & 3;
        if (k < 30)       asm volatile("cp.async.wait_group 2;" ::: "memory");
        else if (k == 30) asm volatile("cp.async.wait_group 1;" ::: "memory");
        else              asm volatile("cp.async.wait_group 0;" ::: "memory");
        __syncthreads();
        if (k + 3 < 32) load_stage((k + 3) & 3, (k + 3) * BK);

        const uint32_t sa = sbase + st * STAGE_B;
        const uint32_t sw = sa + ATILE_B;
#pragma unroll
        for (int s8 = 0; s8 < 4; s8++) {
            const int k0 = s8 * 8;
            uint32_t a[4][4], b[4][2];
#pragma unroll
            for (int mt = 0; mt < 4; mt++) {
                int r = wm + mt * 16 + a_row;
                ldsm_x4(a[mt][0], a[mt][1], a[mt][2], a[mt][3],
                        sa + (uint32_t)(r * 144 + (k0 + a_co) * 4));
            }
#pragma unroll
            for (int p = 0; p < 2; p++) {   // n-tile pairs
                int n = wn + p * 16 + b_row;
                uint32_t r0, r1, r2, r3;
                ldsm_x4(r0, r1, r2, r3,
                        sw + (uint32_t)(n * 144 + (k0 + b_co) * 4));
                b[2 * p][0] = r0;  b[2 * p][1] = r1;
                b[2 * p + 1][0] = r2;  b[2 * p + 1][1] = r3;
            }
#pragma unroll
            for (int mt = 0; mt < 4; mt++)
#pragma unroll
                for (int nt = 0; nt < 4; nt++)
                    mma_tf32(C.c[mt][nt], a[mt], b[nt]);
        }
    }
}

// ===========================================================================
// QKV projection: grid (8, 64, 3), 256 threads
// ===========================================================================
__global__ __launch_bounds__(256)
void qkv_mma_kernel()
{
    extern __shared__ char smem[];
    const int bn = blockIdx.x * 128;
    const int bm = blockIdx.y * 128;
    const int z  = blockIdx.z;
    const float* W   = (z == 0) ? g_Wq : (z == 1) ? g_Wk : g_Wv;
    float*       Dst = (z == 0) ? g_Q  : (z == 1) ? g_K  : g_V;
    const float scale = (z == 0) ? 0.125f : 1.0f;

    CFrag C;
    tf32_gemm_main(g_Xr, W, bm, bn, smem, C);

    const int wid  = threadIdx.x >> 5;
    const int lane = threadIdx.x & 31;
    const int wm = (wid & 1) * 64, wn = (wid >> 1) * 32;

#pragma unroll
    for (int mt = 0; mt < 4; mt++) {
#pragma unroll
        for (int nt = 0; nt < 4; nt++) {
            int n = bn + wn + nt * 8 + 2 * (lane & 3);
            int h = n >> 6, d = n & 63;     // pair stays in one head (n even)
#pragma unroll
            for (int half = 0; half < 2; half++) {
                int m = bm + wm + mt * 16 + (lane >> 2) + half * 8;
                int b = m >> 11, s = m & 2047;
                float* p = &Dst[(((size_t)(b * Hsz + h)) * Ssz + s) * HDsz + d];
                float2 v;
                v.x = C.c[mt][nt][2 * half + 0] * scale;
                v.y = C.c[mt][nt][2 * half + 1] * scale;
                *(float2*)p = v;
            }
        }
    }
}

// ===========================================================================
// Output projection: grid (8, 64), 256 threads -> d_out
// ===========================================================================
__global__ __launch_bounds__(256)
void out_mma_kernel(float* __restrict__ Out)
{
    extern __shared__ char smem[];
    const int bn = blockIdx.x * 128;
    const int bm = blockIdx.y * 128;

    CFrag C;
    tf32_gemm_main(g_AO, g_Wo, bm, bn, smem, C);

    const int wid  = threadIdx.x >> 5;
    const int lane = threadIdx.x & 31;
    const int wm = (wid & 1) * 64, wn = (wid >> 1) * 32;

#pragma unroll
    for (int mt = 0; mt < 4; mt++) {
#pragma unroll
        for (int nt = 0; nt < 4; nt++) {
            int n = bn + wn + nt * 8 + 2 * (lane & 3);
#pragma unroll
            for (int half = 0; half < 2; half++) {
                int m = bm + wm + mt * 16 + (lane >> 2) + half * 8;
                float2 v;
                v.x = C.c[mt][nt][2 * half + 0];
                v.y = C.c[mt][nt][2 * half + 1];
                *(float2*)&Out[(size_t)m * 1024 + n] = v;
            }
        }
    }
}

// ===========================================================================
// RNA-round inputs to tf32 (removes HW truncation bias in mma.sync)
// ===========================================================================
__global__ __launch_bounds__(256)
void round_tf32_kernel(const float* __restrict__ src, int sel, int n)
{
    float* dst = (sel == 0) ? g_Xr : (sel == 1) ? g_Wq :
                 (sel == 2) ? g_Wk : (sel == 3) ? g_Wv : g_Wo;
    int i = (blockIdx.x * 256 + threadIdx.x) * 4;
    if (i < n) {
        float4 v = *(const float4*)(src + i);
        v.x = tf32_rna(v.x); v.y = tf32_rna(v.y);
        v.z = tf32_rna(v.z); v.w = tf32_rna(v.w);
        *(float4*)(dst + i) = v;
    }
}

// ===========================================================================
// Flash attention (fp32, online softmax) — unchanged; tf32-RNA epilogue
// ===========================================================================
__global__ __launch_bounds__(256)
void attn_kernel()
{
    extern __shared__ float smemf[];
    float* Sq = smemf;
    float* Sk = Sq + 64 * 68;
    float* Sv = Sk + 64 * 68;
    float* Sp = Sv + 64 * 68;

    const int t  = threadIdx.x;
    const int qb = blockIdx.x;
    const int bh = blockIdx.y;

    const float* Qp = g_Q + (size_t)bh * (Ssz * HDsz) + qb * (64 * HDsz);
    const float* Kp = g_K + (size_t)bh * (Ssz * HDsz);
    const float* Vp = g_V + (size_t)bh * (Ssz * HDsz);

#pragma unroll
    for (int i = 0; i < 4; i++) {
        int idx = t + i * 256;
        int r   = idx >> 4;
        int dq  = (idx & 15) << 2;
        float4 v = *(const float4*)&Qp[r * 64 + dq];
        Sq[(dq + 0) * 68 + r] = v.x;
        Sq[(dq + 1) * 68 + r] = v.y;
        Sq[(dq + 2) * 68 + r] = v.z;
        Sq[(dq + 3) * 68 + r] = v.w;
    }

    float4 rk[4], rv[4];
    auto ldg_kv = [&](int kb) {
        const float* kp = Kp + kb * 64 * 64;
        const float* vp = Vp + kb * 64 * 64;
#pragma unroll
        for (int i = 0; i < 4; i++) {
            int idx = t + i * 256;
            int r   = idx >> 4;
            int dq  = (idx & 15) << 2;
            rk[i] = *(const float4*)&kp[r * 64 + dq];
            rv[i] = *(const float4*)&vp[r * 64 + dq];
        }
    };
    auto sts_kv = [&]() {
#pragma unroll
        for (int i = 0; i < 4; i++) {
            int idx = t + i * 256;
            int r   = idx >> 4;
            int dq  = (idx & 15) << 2;
            Sk[(dq + 0) * 68 + r] = rk[i].x;
            Sk[(dq + 1) * 68 + r] = rk[i].y;
            Sk[(dq + 2) * 68 + r] = rk[i].z;
            Sk[(dq + 3) * 68 + r] = rk[i].w;
            *(float4*)&Sv[r * 68 + dq] = rv[i];
        }
    };

    ldg_kv(0);
    sts_kv();
    __syncthreads();

    const int rg = t >> 4;
    const int cg = t & 15;
    const int r0 = rg << 2;
    const int c0 = cg << 2;

    float o[4][4];
    float mrow[4], lrow[4];
#pragma unroll
    for (int i = 0; i < 4; i++) {
        mrow[i] = -1e30f;
        lrow[i] = 0.0f;
#pragma unroll
        for (int j = 0; j < 4; j++) o[i][j] = 0.0f;
    }

    for (int kb = 0; kb < 32; kb++) {
        if (kb + 1 < 32) ldg_kv(kb + 1);

        float sc[4][4];
#pragma unroll
        for (int i = 0; i < 4; i++)
#pragma unroll
            for (int j = 0; j < 4; j++) sc[i][j] = 0.0f;

#pragma unroll 16
        for (int d = 0; d < 64; d++) {
            float qa[4], ka[4];
            *(float4*)qa = *(const float4*)&Sq[d * 68 + r0];
            *(float4*)ka = *(const float4*)&Sk[d * 68 + c0];
#pragma unroll
            for (int i = 0; i < 4; i++)
#pragma unroll
                for (int j = 0; j < 4; j++)
                    sc[i][j] += qa[i] * ka[j];
        }

        float mloc[4];
#pragma unroll
        for (int i = 0; i < 4; i++)
            mloc[i] = fmaxf(fmaxf(sc[i][0], sc[i][1]), fmaxf(sc[i][2], sc[i][3]));
#pragma unroll
        for (int off = 1; off < 16; off <<= 1)
#pragma unroll
            for (int i = 0; i < 4; i++)
                mloc[i] = fmaxf(mloc[i], __shfl_xor_sync(0xffffffffu, mloc[i], off));

        float alpha[4], lloc[4];
#pragma unroll
        for (int i = 0; i < 4; i++) {
            float mn = fmaxf(mrow[i], mloc[i]);
            alpha[i] = __expf(mrow[i] - mn);
            mrow[i]  = mn;
            sc[i][0] = __expf(sc[i][0] - mn);
            sc[i][1] = __expf(sc[i][1] - mn);
            sc[i][2] = __expf(sc[i][2] - mn);
            sc[i][3] = __expf(sc[i][3] - mn);
            lloc[i]  = (sc[i][0] + sc[i][1]) + (sc[i][2] + sc[i][3]);
        }
#pragma unroll
        for (int off = 1; off < 16; off <<= 1)
#pragma unroll
            for (int i = 0; i < 4; i++)
                lloc[i] += __shfl_xor_sync(0xffffffffu, lloc[i], off);
#pragma unroll
        for (int i = 0; i < 4; i++) {
            lrow[i] = lrow[i] * alpha[i] + lloc[i];
#pragma unroll
            for (int j = 0; j < 4; j++) o[i][j] *= alpha[i];
        }

#pragma unroll
        for (int i = 0; i < 4; i++)
            *(float4*)&Sp[(r0 + i) * 68 + c0] =
                make_float4(sc[i][0], sc[i][1], sc[i][2], sc[i][3]);
        __syncwarp();

#pragma unroll 4
        for (int c = 0; c < 64; c += 4) {
            float pa[4][4], va[4][4];
#pragma unroll
            for (int i = 0; i < 4; i++)
                *(float4*)pa[i] = *(const float4*)&Sp[(r0 + i) * 68 + c];
#pragma unroll
            for (int jj = 0; jj < 4; jj++)
                *(float4*)va[jj] = *(const float4*)&Sv[(c + jj) * 68 + c0];
#pragma unroll
            for (int i = 0; i < 4; i++)
#pragma unroll
                for (int jj = 0; jj < 4; jj++)
#pragma unroll
                    for (int j = 0; j < 4; j++)
                        o[i][j] += pa[i][jj] * va[jj][j];
        }

        __syncthreads();
        if (kb + 1 < 32) {
            sts_kv();
            __syncthreads();
        }
    }

    const int b = bh >> 4;
    const int h = bh & 15;
#pragma unroll
    for (int i = 0; i < 4; i++) {
        float inv = 1.0f / lrow[i];
        int s = qb * 64 + r0 + i;
        float* p = &g_AO[((size_t)(b * Ssz + s)) * Dsz + h * HDsz + c0];
        *(float4*)p = make_float4(tf32_rna(o[i][0] * inv), tf32_rna(o[i][1] * inv),
                                  tf32_rna(o[i][2] * inv), tf32_rna(o[i][3] * inv));
    }
}

// ===========================================================================
extern "C" void kernel_launch(void* const* d_in, const int* in_sizes, int n_in,
                              void* d_out, int out_size)
{
    const float* X  = (const float*)d_in[0];
    const float* Wq = (const float*)d_in[1];
    const float* Wk = (const float*)d_in[2];
    const float* Wv = (const float*)d_in[3];
    const float* Wo = (const float*)d_in[4];
    float* Out = (float*)d_out;

    const int attn_smem = 4 * 64 * 68 * (int)sizeof(float);   // 69632 B
    cudaFuncSetAttribute(attn_kernel,
                         cudaFuncAttributeMaxDynamicSharedMemorySize, attn_smem);
    cudaFuncSetAttribute(qkv_mma_kernel,
                         cudaFuncAttributeMaxDynamicSharedMemorySize, GSMEM);
    cudaFuncSetAttribute(out_mma_kernel,
                         cudaFuncAttributeMaxDynamicSharedMemorySize, GSMEM);

    // RNA-round tensor-core operands
    round_tf32_kernel<<<Msz * Dsz / 1024, 256>>>(X,  0, Msz * Dsz);
    round_tf32_kernel<<<Dsz * Dsz / 1024, 256>>>(Wq, 1, Dsz * Dsz);
    round_tf32_kernel<<<Dsz * Dsz / 1024, 256>>>(Wk, 2, Dsz * Dsz);
    round_tf32_kernel<<<Dsz * Dsz / 1024, 256>>>(Wv, 3, Dsz * Dsz);
    round_tf32_kernel<<<Dsz * Dsz / 1024, 256>>>(Wo, 4, Dsz * Dsz);

    dim3 gq(8, 64, 3);
    qkv_mma_kernel<<<gq, 256, GSMEM>>>();

    dim3 ga(32, 64);
    attn_kernel<<<ga, 256, attn_smem>>>();

    dim3 go(8, 64);
    out_mma_kernel<<<go, 256, GSMEM>>>(Out);
}

// round 8
// speedup vs baseline: 3.2994x; 2.2607x over previous
#include <cuda_runtime.h>
#include <math.h>
#include <stdint.h>

#define Bsz  4
#define Ssz  2048
#define Dsz  1024
#define Hsz  16
#define HDsz 64
#define Msz  (Bsz * Ssz)   // 8192

// Scratch (device globals: allocation-free rule)
__device__ float g_Q[Msz * Dsz];    // [B,H,S,hd] (tf32-rounded, pre-scaled)
__device__ float g_K[Msz * Dsz];    // [B,H,S,hd] (tf32-rounded)
__device__ float g_V[Msz * Dsz];    // [B,H,S,hd] (tf32-rounded)
__device__ float g_Vt[Msz * Dsz];   // [B,H,hd,S] transposed V
__device__ float g_AO[Msz * Dsz];   // [B,S,H*hd], tf32-rounded
__device__ float g_Xr[Msz * Dsz];   // X rounded to tf32 (RNA)
__device__ float g_Wq[Dsz * Dsz];
__device__ float g_Wk[Dsz * Dsz];
__device__ float g_Wv[Dsz * Dsz];
__device__ float g_Wo[Dsz * Dsz];

// ===========================================================================
// helpers
// ===========================================================================
__device__ __forceinline__ uint32_t smem_u32(const void* p) {
    uint32_t a;
    asm("{ .reg .u64 t; cvta.to.shared.u64 t, %1; cvt.u32.u64 %0, t; }"
        : "=r"(a) : "l"(p));
    return a;
}
__device__ __forceinline__ float tf32_rna(float x) {
    uint32_t u;
    asm("cvt.rna.tf32.f32 %0, %1;" : "=r"(u) : "f"(x));
    return __uint_as_float(u);
}
__device__ __forceinline__ void ldsm_x4(uint32_t& r0, uint32_t& r1,
                                        uint32_t& r2, uint32_t& r3, uint32_t a) {
    asm volatile("ldmatrix.sync.aligned.m8n8.x4.shared.b16 {%0,%1,%2,%3}, [%4];"
                 : "=r"(r0), "=r"(r1), "=r"(r2), "=r"(r3) : "r"(a));
}
__device__ __forceinline__ void mma_tf32(float* c, const uint32_t* a,
                                         const uint32_t* b) {
    asm volatile(
        "mma.sync.aligned.m16n8k8.row.col.f32.tf32.tf32.f32 "
        "{%0,%1,%2,%3}, {%4,%5,%6,%7}, {%8,%9}, {%0,%1,%2,%3};"
        : "+f"(c[0]), "+f"(c[1]), "+f"(c[2]), "+f"(c[3])
        : "r"(a[0]), "r"(a[1]), "r"(a[2]), "r"(a[3]), "r"(b[0]), "r"(b[1]));
}
__device__ __forceinline__ void cp16(uint32_t saddr, const void* gaddr) {
    asm volatile("cp.async.cg.shared.global [%0], [%1], 16;"
                 :: "r"(saddr), "l"(gaddr));
}

// ===========================================================================
// tf32 mma.sync GEMM: D[128,128] = A[bm:,1024] * W[bn:,1024]^T  (NT)
// (validated in R6)
// ===========================================================================
#define BK        32
#define ROWPAD    36
#define ATILE_B   (128 * ROWPAD * 4)        // 18432
#define STAGE_B   (2 * ATILE_B)             // 36864
#define NSTAGE    4
#define GSMEM     (NSTAGE * STAGE_B)        // 147456

struct CFrag { float c[4][4][4]; };

__device__ __forceinline__ void tf32_gemm_main(const float* __restrict__ A,
                                               const float* __restrict__ W,
                                               int bm, int bn, char* smem,
                                               CFrag& C)
{
    const int tid  = threadIdx.x;
    const int wid  = tid >> 5;
    const int lane = tid & 31;
    const int wm   = (wid & 1) * 64;
    const int wn   = (wid >> 1) * 32;
    const uint32_t sbase = smem_u32(smem);

#pragma unroll
    for (int i = 0; i < 4; i++)
#pragma unroll
        for (int j = 0; j < 4; j++)
#pragma unroll
            for (int q = 0; q < 4; q++) C.c[i][j][q] = 0.0f;

    auto load_stage = [&](int st, int k0) {
        const uint32_t sb = sbase + st * STAGE_B;
#pragma unroll
        for (int i = 0; i < 4; i++) {
            int id  = tid + i * 256;
            int row = id >> 3;
            int ch  = id & 7;
            uint32_t so = (uint32_t)(row * 144 + ch * 16);
            cp16(sb + so,            A + (size_t)(bm + row) * 1024 + k0 + ch * 4);
            cp16(sb + ATILE_B + so,  W + (size_t)(bn + row) * 1024 + k0 + ch * 4);
        }
        asm volatile("cp.async.commit_group;" ::: "memory");
    };

    load_stage(0, 0);
    load_stage(1, BK);
    load_stage(2, 2 * BK);

    const int a_row = (lane & 7) + ((lane >> 3) & 1) * 8;
    const int a_co  = (lane >> 4) * 4;
    const int b_row = (lane & 7) + (lane >> 4) * 8;
    const int b_co  = ((lane >> 3) & 1) * 4;

    for (int k = 0; k < 32; k++) {
        const int st = k & 3;
        if (k < 30)       asm volatile("cp.async.wait_group 2;" ::: "memory");
        else if (k == 30) asm volatile("cp.async.wait_group 1;" ::: "memory");
        else              asm volatile("cp.async.wait_group 0;" ::: "memory");
        __syncthreads();
        if (k + 3 < 32) load_stage((k + 3) & 3, (k + 3) * BK);

        const uint32_t sa = sbase + st * STAGE_B;
        const uint32_t sw = sa + ATILE_B;
#pragma unroll
        for (int s8 = 0; s8 < 4; s8++) {
            const int k0 = s8 * 8;
            uint32_t a[4][4], b[4][2];
#pragma unroll
            for (int mt = 0; mt < 4; mt++) {
                int r = wm + mt * 16 + a_row;
                ldsm_x4(a[mt][0], a[mt][1], a[mt][2], a[mt][3],
                        sa + (uint32_t)(r * 144 + (k0 + a_co) * 4));
            }
#pragma unroll
            for (int p = 0; p < 2; p++) {
                int n = wn + p * 16 + b_row;
                uint32_t r0, r1, r2, r3;
                ldsm_x4(r0, r1, r2, r3,
                        sw + (uint32_t)(n * 144 + (k0 + b_co) * 4));
                b[2 * p][0] = r0;  b[2 * p][1] = r1;
                b[2 * p + 1][0] = r2;  b[2 * p + 1][1] = r3;
            }
#pragma unroll
            for (int mt = 0; mt < 4; mt++)
#pragma unroll
                for (int nt = 0; nt < 4; nt++)
                    mma_tf32(C.c[mt][nt], a[mt], b[nt]);
        }
    }
}

// ===========================================================================
// QKV projection: grid (8, 64, 3), 256 threads. Outputs RNA-rounded to tf32.
// ===========================================================================
__global__ __launch_bounds__(256)
void qkv_mma_kernel()
{
    extern __shared__ char smem[];
    const int bn = blockIdx.x * 128;
    const int bm = blockIdx.y * 128;
    const int z  = blockIdx.z;
    const float* W   = (z == 0) ? g_Wq : (z == 1) ? g_Wk : g_Wv;
    float*       Dst = (z == 0) ? g_Q  : (z == 1) ? g_K  : g_V;
    const float scale = (z == 0) ? 0.125f : 1.0f;

    CFrag C;
    tf32_gemm_main(g_Xr, W, bm, bn, smem, C);

    const int wid  = threadIdx.x >> 5;
    const int lane = threadIdx.x & 31;
    const int wm = (wid & 1) * 64, wn = (wid >> 1) * 32;

#pragma unroll
    for (int mt = 0; mt < 4; mt++) {
#pragma unroll
        for (int nt = 0; nt < 4; nt++) {
            int n = bn + wn + nt * 8 + 2 * (lane & 3);
            int h = n >> 6, d = n & 63;
#pragma unroll
            for (int half = 0; half < 2; half++) {
                int m = bm + wm + mt * 16 + (lane >> 2) + half * 8;
                int b = m >> 11, s = m & 2047;
                float* p = &Dst[(((size_t)(b * Hsz + h)) * Ssz + s) * HDsz + d];
                float2 v;
                v.x = tf32_rna(C.c[mt][nt][2 * half + 0] * scale);
                v.y = tf32_rna(C.c[mt][nt][2 * half + 1] * scale);
                *(float2*)p = v;
            }
        }
    }
}

// ===========================================================================
// Output projection: grid (8, 64), 256 threads -> d_out
// ===========================================================================
__global__ __launch_bounds__(256)
void out_mma_kernel(float* __restrict__ Out)
{
    extern __shared__ char smem[];
    const int bn = blockIdx.x * 128;
    const int bm = blockIdx.y * 128;

    CFrag C;
    tf32_gemm_main(g_AO, g_Wo, bm, bn, smem, C);

    const int wid  = threadIdx.x >> 5;
    const int lane = threadIdx.x & 31;
    const int wm = (wid & 1) * 64, wn = (wid >> 1) * 32;

#pragma unroll
    for (int mt = 0; mt < 4; mt++) {
#pragma unroll
        for (int nt = 0; nt < 4; nt++) {
            int n = bn + wn + nt * 8 + 2 * (lane & 3);
#pragma unroll
            for (int half = 0; half < 2; half++) {
                int m = bm + wm + mt * 16 + (lane >> 2) + half * 8;
                float2 v;
                v.x = C.c[mt][nt][2 * half + 0];
                v.y = C.c[mt][nt][2 * half + 1];
                *(float2*)&Out[(size_t)m * 1024 + n] = v;
            }
        }
    }
}

// ===========================================================================
// RNA-round inputs to tf32
// ===========================================================================
__global__ __launch_bounds__(256)
void round_tf32_kernel(const float* __restrict__ src, int sel, int n)
{
    float* dst = (sel == 0) ? g_Xr : (sel == 1) ? g_Wq :
                 (sel == 2) ? g_Wk : (sel == 3) ? g_Wv : g_Wo;
    int i = (blockIdx.x * 256 + threadIdx.x) * 4;
    if (i < n) {
        float4 v = *(const float4*)(src + i);
        v.x = tf32_rna(v.x); v.y = tf32_rna(v.y);
        v.z = tf32_rna(v.z); v.w = tf32_rna(v.w);
        *(float4*)(dst + i) = v;
    }
}

// ===========================================================================
// V transpose: g_V[bh][s][d] -> g_Vt[bh][d][s].  grid (64, 2, 64), block 32x8
// ===========================================================================
__global__ __launch_bounds__(256)
void vt_kernel()
{
    __shared__ float t[32][33];
    const int bh = blockIdx.z;
    const int s0 = blockIdx.x * 32, d0 = blockIdx.y * 32;
    const float* V  = g_V  + (size_t)bh * (Ssz * HDsz);
    float*       Vt = g_Vt + (size_t)bh * (HDsz * Ssz);
    const int tx = threadIdx.x, ty = threadIdx.y;
#pragma unroll
    for (int i = 0; i < 4; i++)
        t[ty + i * 8][tx] = V[(size_t)(s0 + ty + i * 8) * 64 + d0 + tx];
    __syncthreads();
#pragma unroll
    for (int i = 0; i < 4; i++)
        Vt[(size_t)(d0 + ty + i * 8) * Ssz + s0 + tx] = t[tx][ty + i * 8];
}

// ===========================================================================
// Flash attention, tf32 mma.sync.  grid (16, 64), 256 threads = 8 warps.
// CTA: 128 q rows; warp: 16 q rows. KV blocks of 64, double-buffered cp.async.
// Smem rows stride 272B (68 floats): 16B-aligned, conflict-free LDSM phases.
// ===========================================================================
#define ARS   68                          // floats per smem row
#define ARB   272                         // bytes per smem row
#define KVT_B (64 * ARB)                  // one K or Vt tile: 17408 B
#define ASMEM (4 * KVT_B + 128 * ARB)     // 2xK + 2xVt + P: 104448 B

__global__ __launch_bounds__(256, 1)
void attn_mma_kernel()
{
    extern __shared__ float sm[];
    float* sP = sm + 4 * 64 * ARS;        // [128][68], also Q staging

    const int tid = threadIdx.x;
    const int w   = tid >> 5;
    const int lane = tid & 31;
    const int qb = blockIdx.x;
    const int bh = blockIdx.y;

    const float* Qp  = g_Q  + (size_t)bh * (Ssz * HDsz) + (size_t)qb * 128 * HDsz;
    const float* Kp  = g_K  + (size_t)bh * (Ssz * HDsz);
    const float* Vtp = g_Vt + (size_t)bh * (HDsz * Ssz);

    const uint32_t sKb = smem_u32(sm);
    const uint32_t sVb = sKb + 2 * KVT_B;
    const uint32_t sPb = sKb + 4 * KVT_B;

    // ---- stage Q, build persistent A-fragments (32 regs) ----
#pragma unroll
    for (int i = 0; i < 8; i++) {
        int id = tid + i * 256;           // 0..2047
        int r = id >> 4, ch = id & 15;
        *(float4*)&sP[r * ARS + ch * 4] = *(const float4*)&Qp[r * 64 + ch * 4];
    }
    __syncthreads();

    const int a_row = (lane & 7) + ((lane >> 3) & 1) * 8;
    const int a_co  = (lane >> 4) * 4;
    const int b_row = (lane & 7) + (lane >> 4) * 8;
    const int b_co  = ((lane >> 3) & 1) * 4;

    uint32_t qf[8][4];
#pragma unroll
    for (int kc = 0; kc < 8; kc++)
        ldsm_x4(qf[kc][0], qf[kc][1], qf[kc][2], qf[kc][3],
                sPb + (uint32_t)((w * 16 + a_row) * ARB + (kc * 8 + a_co) * 4));
    __syncthreads();                      // P region now free for reuse

    // ---- KV double-buffered loader ----
    auto load_kv = [&](int kb, int buf) {
        const float* kg = Kp  + (size_t)kb * 64 * 64;
        const float* vg = Vtp + kb * 64;
        const uint32_t kd = sKb + buf * KVT_B;
        const uint32_t vd = sVb + buf * KVT_B;
#pragma unroll
        for (int i = 0; i < 4; i++) {
            int id = tid + i * 256;       // 0..1023
            int r = id >> 4, ch = id & 15;
            cp16(kd + r * ARB + ch * 16, kg + r * 64 + ch * 4);
            cp16(vd + r * ARB + ch * 16, vg + (size_t)r * Ssz + ch * 4);
        }
        asm volatile("cp.async.commit_group;" ::: "memory");
    };

    load_kv(0, 0);
    load_kv(1, 1);

    float m[2] = {-1e30f, -1e30f}, l[2] = {0.0f, 0.0f};
    float of[8][4];
#pragma unroll
    for (int nt = 0; nt < 8; nt++)
#pragma unroll
        for (int q = 0; q < 4; q++) of[nt][q] = 0.0f;

    const uint32_t pw = sPb + (uint32_t)(w * 16) * ARB;   // warp-private P rows

    for (int kb = 0; kb < 32; kb++) {
        const int buf = kb & 1;
        if (kb < 31) asm volatile("cp.async.wait_group 1;" ::: "memory");
        else         asm volatile("cp.async.wait_group 0;" ::: "memory");
        __syncthreads();

        const uint32_t kbase = sKb + buf * KVT_B;
        const uint32_t vbase = sVb + buf * KVT_B;

        // ---- S = Q K^T : 64 mma ----
        float sc[8][4];
#pragma unroll
        for (int nt = 0; nt < 8; nt++)
#pragma unroll
            for (int q = 0; q < 4; q++) sc[nt][q] = 0.0f;

#pragma unroll
        for (int kc = 0; kc < 8; kc++) {
#pragma unroll
            for (int p = 0; p < 4; p++) {
                uint32_t r0, r1, r2, r3;
                ldsm_x4(r0, r1, r2, r3,
                        kbase + (uint32_t)((p * 16 + b_row) * ARB + (kc * 8 + b_co) * 4));
                uint32_t b0[2] = {r0, r1}, b1[2] = {r2, r3};
                mma_tf32(sc[2 * p],     qf[kc], b0);
                mma_tf32(sc[2 * p + 1], qf[kc], b1);
            }
        }

        // ---- online softmax (rows: lane>>2, +8; quad reduction) ----
        float ml0 = -1e30f, ml1 = -1e30f;
#pragma unroll
        for (int nt = 0; nt < 8; nt++) {
            ml0 = fmaxf(ml0, fmaxf(sc[nt][0], sc[nt][1]));
            ml1 = fmaxf(ml1, fmaxf(sc[nt][2], sc[nt][3]));
        }
        ml0 = fmaxf(ml0, __shfl_xor_sync(0xffffffffu, ml0, 1));
        ml0 = fmaxf(ml0, __shfl_xor_sync(0xffffffffu, ml0, 2));
        ml1 = fmaxf(ml1, __shfl_xor_sync(0xffffffffu, ml1, 1));
        ml1 = fmaxf(ml1, __shfl_xor_sync(0xffffffffu, ml1, 2));

        const float mn0 = fmaxf(m[0], ml0), mn1 = fmaxf(m[1], ml1);
        const float a0 = __expf(m[0] - mn0), a1 = __expf(m[1] - mn1);
        m[0] = mn0; m[1] = mn1;

        float ll0 = 0.0f, ll1 = 0.0f;
#pragma unroll
        for (int nt = 0; nt < 8; nt++) {
            sc[nt][0] = __expf(sc[nt][0] - mn0);
            sc[nt][1] = __expf(sc[nt][1] - mn0);
            sc[nt][2] = __expf(sc[nt][2] - mn1);
            sc[nt][3] = __expf(sc[nt][3] - mn1);
            ll0 += sc[nt][0] + sc[nt][1];
            ll1 += sc[nt][2] + sc[nt][3];
        }
        ll0 += __shfl_xor_sync(0xffffffffu, ll0, 1);
        ll0 += __shfl_xor_sync(0xffffffffu, ll0, 2);
        ll1 += __shfl_xor_sync(0xffffffffu, ll1, 1);
        ll1 += __shfl_xor_sync(0xffffffffu, ll1, 2);
        l[0] = l[0] * a0 + ll0;
        l[1] = l[1] * a1 + ll1;

#pragma unroll
        for (int nt = 0; nt < 8; nt++) {
            of[nt][0] *= a0; of[nt][1] *= a0;
            of[nt][2] *= a1; of[nt][3] *= a1;
        }

        // ---- P -> warp-private smem (RNA-rounded), reload as A-fragments ----
        {
            const uint32_t r0a = pw + (uint32_t)((lane >> 2) * ARB + 2 * (lane & 3) * 4);
#pragma unroll
            for (int nt = 0; nt < 8; nt++) {
                float2 v0 = make_float2(tf32_rna(sc[nt][0]), tf32_rna(sc[nt][1]));
                float2 v1 = make_float2(tf32_rna(sc[nt][2]), tf32_rna(sc[nt][3]));
                asm volatile("st.shared.v2.f32 [%0], {%1, %2};"
                             :: "r"(r0a + nt * 32), "f"(v0.x), "f"(v0.y));
                asm volatile("st.shared.v2.f32 [%0], {%1, %2};"
                             :: "r"(r0a + 8 * ARB + nt * 32), "f"(v1.x), "f"(v1.y));
            }
        }
        __syncwarp();

        // ---- O += P V : 64 mma ----
#pragma unroll
        for (int kc = 0; kc < 8; kc++) {
            uint32_t af[4];
            ldsm_x4(af[0], af[1], af[2], af[3],
                    pw + (uint32_t)(a_row * ARB + (kc * 8 + a_co) * 4));
#pragma unroll
            for (int p = 0; p < 4; p++) {
                uint32_t r0, r1, r2, r3;
                ldsm_x4(r0, r1, r2, r3,
                        vbase + (uint32_t)((p * 16 + b_row) * ARB + (kc * 8 + b_co) * 4));
                uint32_t b0[2] = {r0, r1}, b1[2] = {r2, r3};
                mma_tf32(of[2 * p],     af, b0);
                mma_tf32(of[2 * p + 1], af, b1);
            }
        }

        __syncthreads();                  // everyone done with buf
        if (kb + 2 < 32) load_kv(kb + 2, buf);
    }

    // ---- epilogue: normalize, RNA-round, write g_AO[b, s, h*64+n] ----
    const float inv0 = 1.0f / l[0], inv1 = 1.0f / l[1];
    const int b = bh >> 4, h = bh & 15;
    const int s0 = qb * 128 + w * 16 + (lane >> 2);
#pragma unroll
    for (int nt = 0; nt < 8; nt++) {
        int n = h * 64 + nt * 8 + 2 * (lane & 3);
        float2 v0, v1;
        v0.x = tf32_rna(of[nt][0] * inv0);
        v0.y = tf32_rna(of[nt][1] * inv0);
        v1.x = tf32_rna(of[nt][2] * inv1);
        v1.y = tf32_rna(of[nt][3] * inv1);
        *(float2*)&g_AO[(size_t)(b * Ssz + s0) * Dsz + n]       = v0;
        *(float2*)&g_AO[(size_t)(b * Ssz + s0 + 8) * Dsz + n]   = v1;
    }
}

// ===========================================================================
extern "C" void kernel_launch(void* const* d_in, const int* in_sizes, int n_in,
                              void* d_out, int out_size)
{
    const float* X  = (const float*)d_in[0];
    const float* Wq = (const float*)d_in[1];
    const float* Wk = (const float*)d_in[2];
    const float* Wv = (const float*)d_in[3];
    const float* Wo = (const float*)d_in[4];
    float* Out = (float*)d_out;

    cudaFuncSetAttribute(qkv_mma_kernel,
                         cudaFuncAttributeMaxDynamicSharedMemorySize, GSMEM);
    cudaFuncSetAttribute(out_mma_kernel,
                         cudaFuncAttributeMaxDynamicSharedMemorySize, GSMEM);
    cudaFuncSetAttribute(attn_mma_kernel,
                         cudaFuncAttributeMaxDynamicSharedMemorySize, ASMEM);

    round_tf32_kernel<<<Msz * Dsz / 1024, 256>>>(X,  0, Msz * Dsz);
    round_tf32_kernel<<<Dsz * Dsz / 1024, 256>>>(Wq, 1, Dsz * Dsz);
    round_tf32_kernel<<<Dsz * Dsz / 1024, 256>>>(Wk, 2, Dsz * Dsz);
    round_tf32_kernel<<<Dsz * Dsz / 1024, 256>>>(Wv, 3, Dsz * Dsz);
    round_tf32_kernel<<<Dsz * Dsz / 1024, 256>>>(Wo, 4, Dsz * Dsz);

    dim3 gq(8, 64, 3);
    qkv_mma_kernel<<<gq, 256, GSMEM>>>();

    dim3 gt(64, 2, 64);
    vt_kernel<<<gt, dim3(32, 8)>>>();

    dim3 ga(16, 64);
    attn_mma_kernel<<<ga, 256, ASMEM>>>();

    dim3 go(8, 64);
    out_mma_kernel<<<go, 256, GSMEM>>>(Out);
}

// round 9
// speedup vs baseline: 3.4971x; 1.0599x over previous
#include <cuda_runtime.h>
#include <math.h>
#include <stdint.h>

#define Bsz  4
#define Ssz  2048
#define Dsz  1024
#define Hsz  16
#define HDsz 64
#define Msz  (Bsz * Ssz)   // 8192

// Scratch (device globals: allocation-free rule)
__device__ float g_Q[Msz * Dsz];    // [B,H,S,hd] (tf32-rounded, scaled log2e/8)
__device__ float g_K[Msz * Dsz];    // [B,H,S,hd] (tf32-rounded)
__device__ float g_V[Msz * Dsz];    // [B,H,S,hd] (tf32-rounded)
__device__ float g_Vt[Msz * Dsz];   // [B,H,hd,S] transposed V
__device__ float g_AO[Msz * Dsz];   // [B,S,H*hd], tf32-rounded
__device__ float g_Xr[Msz * Dsz];   // X rounded to tf32 (RNA)
__device__ float g_Wq[Dsz * Dsz];
__device__ float g_Wk[Dsz * Dsz];
__device__ float g_Wv[Dsz * Dsz];
__device__ float g_Wo[Dsz * Dsz];

// ===========================================================================
// helpers
// ===========================================================================
__device__ __forceinline__ uint32_t smem_u32(const void* p) {
    uint32_t a;
    asm("{ .reg .u64 t; cvta.to.shared.u64 t, %1; cvt.u32.u64 %0, t; }"
        : "=r"(a) : "l"(p));
    return a;
}
__device__ __forceinline__ float tf32_rna(float x) {
    uint32_t u;
    asm("cvt.rna.tf32.f32 %0, %1;" : "=r"(u) : "f"(x));
    return __uint_as_float(u);
}
__device__ __forceinline__ void ldsm_x4(uint32_t& r0, uint32_t& r1,
                                        uint32_t& r2, uint32_t& r3, uint32_t a) {
    asm volatile("ldmatrix.sync.aligned.m8n8.x4.shared.b16 {%0,%1,%2,%3}, [%4];"
                 : "=r"(r0), "=r"(r1), "=r"(r2), "=r"(r3) : "r"(a));
}
__device__ __forceinline__ void mma_tf32(float* c, const uint32_t* a,
                                         const uint32_t* b) {
    asm volatile(
        "mma.sync.aligned.m16n8k8.row.col.f32.tf32.tf32.f32 "
        "{%0,%1,%2,%3}, {%4,%5,%6,%7}, {%8,%9}, {%0,%1,%2,%3};"
        : "+f"(c[0]), "+f"(c[1]), "+f"(c[2]), "+f"(c[3])
        : "r"(a[0]), "r"(a[1]), "r"(a[2]), "r"(a[3]), "r"(b[0]), "r"(b[1]));
}
__device__ __forceinline__ void cp16(uint32_t saddr, const void* gaddr) {
    asm volatile("cp.async.cg.shared.global [%0], [%1], 16;"
                 :: "r"(saddr), "l"(gaddr));
}

// ===========================================================================
// tf32 mma.sync GEMM: D[128,128] = A[bm:,1024] * W[bn:,1024]^T  (NT)
// 2-stage cp.async pipeline, 2 CTAs/SM for barrier-latency interleave.
// ===========================================================================
#define BK        32
#define ROWPAD    36
#define ATILE_B   (128 * ROWPAD * 4)        // 18432
#define STAGE_B   (2 * ATILE_B)             // 36864
#define GSMEM     (2 * STAGE_B)             // 73728

struct CFrag { float c[4][4][4]; };

__device__ __forceinline__ void tf32_gemm_main(const float* __restrict__ A,
                                               const float* __restrict__ W,
                                               int bm, int bn, char* smem,
                                               CFrag& C)
{
    const int tid  = threadIdx.x;
    const int wid  = tid >> 5;
    const int lane = tid & 31;
    const int wm   = (wid & 1) * 64;
    const int wn   = (wid >> 1) * 32;
    const uint32_t sbase = smem_u32(smem);

#pragma unroll
    for (int i = 0; i < 4; i++)
#pragma unroll
        for (int j = 0; j < 4; j++)
#pragma unroll
            for (int q = 0; q < 4; q++) C.c[i][j][q] = 0.0f;

    auto load_stage = [&](int st, int k0) {
        const uint32_t sb = sbase + st * STAGE_B;
#pragma unroll
        for (int i = 0; i < 4; i++) {
            int id  = tid + i * 256;
            int row = id >> 3;
            int ch  = id & 7;
            uint32_t so = (uint32_t)(row * 144 + ch * 16);
            cp16(sb + so,            A + (size_t)(bm + row) * 1024 + k0 + ch * 4);
            cp16(sb + ATILE_B + so,  W + (size_t)(bn + row) * 1024 + k0 + ch * 4);
        }
        asm volatile("cp.async.commit_group;" ::: "memory");
    };

    load_stage(0, 0);
    load_stage(1, BK);

    const int a_row = (lane & 7) + ((lane >> 3) & 1) * 8;
    const int a_co  = (lane >> 4) * 4;
    const int b_row = (lane & 7) + (lane >> 4) * 8;
    const int b_co  = ((lane >> 3) & 1) * 4;

    for (int k = 0; k < 32; k++) {
        const int st = k & 1;
        if (k < 31) asm volatile("cp.async.wait_group 1;" ::: "memory");
        else        asm volatile("cp.async.wait_group 0;" ::: "memory");
        __syncthreads();

        const uint32_t sa = sbase + st * STAGE_B;
        const uint32_t sw = sa + ATILE_B;
#pragma unroll
        for (int s8 = 0; s8 < 4; s8++) {
            const int k0 = s8 * 8;
            uint32_t a[4][4], b[4][2];
#pragma unroll
            for (int mt = 0; mt < 4; mt++) {
                int r = wm + mt * 16 + a_row;
                ldsm_x4(a[mt][0], a[mt][1], a[mt][2], a[mt][3],
                        sa + (uint32_t)(r * 144 + (k0 + a_co) * 4));
            }
#pragma unroll
            for (int p = 0; p < 2; p++) {
                int n = wn + p * 16 + b_row;
                uint32_t r0, r1, r2, r3;
                ldsm_x4(r0, r1, r2, r3,
                        sw + (uint32_t)(n * 144 + (k0 + b_co) * 4));
                b[2 * p][0] = r0;  b[2 * p][1] = r1;
                b[2 * p + 1][0] = r2;  b[2 * p + 1][1] = r3;
            }
#pragma unroll
            for (int mt = 0; mt < 4; mt++)
#pragma unroll
                for (int nt = 0; nt < 4; nt++)
                    mma_tf32(C.c[mt][nt], a[mt], b[nt]);
        }

        __syncthreads();                  // readers done before refill
        if (k + 2 < 32) load_stage((k + 2) & 1, (k + 2) * BK);
    }
}

// ===========================================================================
// QKV projection: grid (8, 64, 3). Outputs RNA-rounded tf32.
// Q scaled by log2(e)/8 so attention softmax runs in exp2 domain.
// ===========================================================================
#define QSCALE 0.18033688011112042f    // log2(e) / 8

__global__ __launch_bounds__(256, 2)
void qkv_mma_kernel()
{
    extern __shared__ char smem[];
    const int bn = blockIdx.x * 128;
    const int bm = blockIdx.y * 128;
    const int z  = blockIdx.z;
    const float* W   = (z == 0) ? g_Wq : (z == 1) ? g_Wk : g_Wv;
    float*       Dst = (z == 0) ? g_Q  : (z == 1) ? g_K  : g_V;
    const float scale = (z == 0) ? QSCALE : 1.0f;

    CFrag C;
    tf32_gemm_main(g_Xr, W, bm, bn, smem, C);

    const int wid  = threadIdx.x >> 5;
    const int lane = threadIdx.x & 31;
    const int wm = (wid & 1) * 64, wn = (wid >> 1) * 32;

#pragma unroll
    for (int mt = 0; mt < 4; mt++) {
#pragma unroll
        for (int nt = 0; nt < 4; nt++) {
            int n = bn + wn + nt * 8 + 2 * (lane & 3);
            int h = n >> 6, d = n & 63;
#pragma unroll
            for (int half = 0; half < 2; half++) {
                int m = bm + wm + mt * 16 + (lane >> 2) + half * 8;
                int b = m >> 11, s = m & 2047;
                float* p = &Dst[(((size_t)(b * Hsz + h)) * Ssz + s) * HDsz + d];
                float2 v;
                v.x = tf32_rna(C.c[mt][nt][2 * half + 0] * scale);
                v.y = tf32_rna(C.c[mt][nt][2 * half + 1] * scale);
                *(float2*)p = v;
            }
        }
    }
}

// ===========================================================================
// Output projection: grid (8, 64) -> d_out
// ===========================================================================
__global__ __launch_bounds__(256, 2)
void out_mma_kernel(float* __restrict__ Out)
{
    extern __shared__ char smem[];
    const int bn = blockIdx.x * 128;
    const int bm = blockIdx.y * 128;

    CFrag C;
    tf32_gemm_main(g_AO, g_Wo, bm, bn, smem, C);

    const int wid  = threadIdx.x >> 5;
    const int lane = threadIdx.x & 31;
    const int wm = (wid & 1) * 64, wn = (wid >> 1) * 32;

#pragma unroll
    for (int mt = 0; mt < 4; mt++) {
#pragma unroll
        for (int nt = 0; nt < 4; nt++) {
            int n = bn + wn + nt * 8 + 2 * (lane & 3);
#pragma unroll
            for (int half = 0; half < 2; half++) {
                int m = bm + wm + mt * 16 + (lane >> 2) + half * 8;
                float2 v;
                v.x = C.c[mt][nt][2 * half + 0];
                v.y = C.c[mt][nt][2 * half + 1];
                *(float2*)&Out[(size_t)m * 1024 + n] = v;
            }
        }
    }
}

// ===========================================================================
// Merged RNA-rounding: X (8M) then Wq/Wk/Wv/Wo (1M each), one launch.
// ===========================================================================
#define XN (Msz * Dsz)        // 8388608
#define WN (Dsz * Dsz)        // 1048576

__global__ __launch_bounds__(256)
void round_all_kernel(const float* __restrict__ X,  const float* __restrict__ Wq,
                      const float* __restrict__ Wk, const float* __restrict__ Wv,
                      const float* __restrict__ Wo)
{
    int i = (blockIdx.x * 256 + threadIdx.x) * 4;
    const float* src;
    float* dst;
    if (i < XN)               { src = X  + i;               dst = g_Xr + i; }
    else if (i < XN + WN)     { src = Wq + (i - XN);        dst = g_Wq + (i - XN); }
    else if (i < XN + 2 * WN) { src = Wk + (i - XN - WN);   dst = g_Wk + (i - XN - WN); }
    else if (i < XN + 3 * WN) { src = Wv + (i - XN - 2*WN); dst = g_Wv + (i - XN - 2*WN); }
    else                      { src = Wo + (i - XN - 3*WN); dst = g_Wo + (i - XN - 3*WN); }
    float4 v = *(const float4*)src;
    v.x = tf32_rna(v.x); v.y = tf32_rna(v.y);
    v.z = tf32_rna(v.z); v.w = tf32_rna(v.w);
    *(float4*)dst = v;
}

// ===========================================================================
// V transpose: g_V[bh][s][d] -> g_Vt[bh][d][s]
// ===========================================================================
__global__ __launch_bounds__(256)
void vt_kernel()
{
    __shared__ float t[32][33];
    const int bh = blockIdx.z;
    const int s0 = blockIdx.x * 32, d0 = blockIdx.y * 32;
    const float* V  = g_V  + (size_t)bh * (Ssz * HDsz);
    float*       Vt = g_Vt + (size_t)bh * (HDsz * Ssz);
    const int tx = threadIdx.x, ty = threadIdx.y;
#pragma unroll
    for (int i = 0; i < 4; i++)
        t[ty + i * 8][tx] = V[(size_t)(s0 + ty + i * 8) * 64 + d0 + tx];
    __syncthreads();
#pragma unroll
    for (int i = 0; i < 4; i++)
        Vt[(size_t)(d0 + ty + i * 8) * Ssz + s0 + tx] = t[tx][ty + i * 8];
}

// ===========================================================================
// Flash attention, tf32 mma.sync.  grid (16, 64), 256 threads = 8 warps.
// 3 KV buffers, ONE syncthreads/iter, refill issued before compute.
// Scores arrive in log2 domain (Q pre-scaled) -> exp2f softmax.
// ===========================================================================
#define ARS   68
#define ARB   272
#define KVT_B (64 * ARB)                   // 17408
#define ASMEM (6 * KVT_B + 128 * ARB)      // 139264

__global__ __launch_bounds__(256, 1)
void attn_mma_kernel()
{
    extern __shared__ float sm[];
    float* sP = sm + 6 * 64 * ARS;         // [128][68], also Q staging

    const int tid = threadIdx.x;
    const int w   = tid >> 5;
    const int lane = tid & 31;
    const int qb = blockIdx.x;
    const int bh = blockIdx.y;

    const float* Qp  = g_Q  + (size_t)bh * (Ssz * HDsz) + (size_t)qb * 128 * HDsz;
    const float* Kp  = g_K  + (size_t)bh * (Ssz * HDsz);
    const float* Vtp = g_Vt + (size_t)bh * (HDsz * Ssz);

    const uint32_t sKb = smem_u32(sm);
    const uint32_t sVb = sKb + 3 * KVT_B;
    const uint32_t sPb = sKb + 6 * KVT_B;

    // ---- stage Q, build persistent A-fragments ----
#pragma unroll
    for (int i = 0; i < 8; i++) {
        int id = tid + i * 256;
        int r = id >> 4, ch = id & 15;
        *(float4*)&sP[r * ARS + ch * 4] = *(const float4*)&Qp[r * 64 + ch * 4];
    }
    __syncthreads();

    const int a_row = (lane & 7) + ((lane >> 3) & 1) * 8;
    const int a_co  = (lane >> 4) * 4;
    const int b_row = (lane & 7) + (lane >> 4) * 8;
    const int b_co  = ((lane >> 3) & 1) * 4;

    uint32_t qf[8][4];
#pragma unroll
    for (int kc = 0; kc < 8; kc++)
        ldsm_x4(qf[kc][0], qf[kc][1], qf[kc][2], qf[kc][3],
                sPb + (uint32_t)((w * 16 + a_row) * ARB + (kc * 8 + a_co) * 4));
    __syncthreads();

    auto load_kv = [&](int kb, int buf) {
        const float* kg = Kp  + (size_t)kb * 64 * 64;
        const float* vg = Vtp + kb * 64;
        const uint32_t kd = sKb + buf * KVT_B;
        const uint32_t vd = sVb + buf * KVT_B;
#pragma unroll
        for (int i = 0; i < 4; i++) {
            int id = tid + i * 256;
            int r = id >> 4, ch = id & 15;
            cp16(kd + r * ARB + ch * 16, kg + r * 64 + ch * 4);
            cp16(vd + r * ARB + ch * 16, vg + (size_t)r * Ssz + ch * 4);
        }
        asm volatile("cp.async.commit_group;" ::: "memory");
    };

    load_kv(0, 0);
    load_kv(1, 1);

    float m[2] = {-1e30f, -1e30f}, l[2] = {0.0f, 0.0f};
    float of[8][4];
#pragma unroll
    for (int nt = 0; nt < 8; nt++)
#pragma unroll
        for (int q = 0; q < 4; q++) of[nt][q] = 0.0f;

    const uint32_t pw = sPb + (uint32_t)(w * 16) * ARB;

    int buf = 0;
    for (int kb = 0; kb < 32; kb++) {
        // pending groups at top: {kb, kb+1}
        if (kb < 31) asm volatile("cp.async.wait_group 1;" ::: "memory");
        else         asm volatile("cp.async.wait_group 0;" ::: "memory");
        __syncthreads();                  // data visible; prev readers of refill slot done
        if (kb + 2 < 32) {
            int nb = buf + 2; if (nb >= 3) nb -= 3;
            load_kv(kb + 2, nb);          // overlaps this iteration's compute
        }

        const uint32_t kbase = sKb + buf * KVT_B;
        const uint32_t vbase = sVb + buf * KVT_B;

        // ---- S = Q K^T (log2 domain) ----
        float sc[8][4];
#pragma unroll
        for (int nt = 0; nt < 8; nt++)
#pragma unroll
            for (int q = 0; q < 4; q++) sc[nt][q] = 0.0f;

#pragma unroll
        for (int kc = 0; kc < 8; kc++) {
#pragma unroll
            for (int p = 0; p < 4; p++) {
                uint32_t r0, r1, r2, r3;
                ldsm_x4(r0, r1, r2, r3,
                        kbase + (uint32_t)((p * 16 + b_row) * ARB + (kc * 8 + b_co) * 4));
                uint32_t b0[2] = {r0, r1}, b1[2] = {r2, r3};
                mma_tf32(sc[2 * p],     qf[kc], b0);
                mma_tf32(sc[2 * p + 1], qf[kc], b1);
            }
        }

        // ---- online softmax in exp2 domain ----
        float ml0 = -1e30f, ml1 = -1e30f;
#pragma unroll
        for (int nt = 0; nt < 8; nt++) {
            ml0 = fmaxf(ml0, fmaxf(sc[nt][0], sc[nt][1]));
            ml1 = fmaxf(ml1, fmaxf(sc[nt][2], sc[nt][3]));
        }
        ml0 = fmaxf(ml0, __shfl_xor_sync(0xffffffffu, ml0, 1));
        ml0 = fmaxf(ml0, __shfl_xor_sync(0xffffffffu, ml0, 2));
        ml1 = fmaxf(ml1, __shfl_xor_sync(0xffffffffu, ml1, 1));
        ml1 = fmaxf(ml1, __shfl_xor_sync(0xffffffffu, ml1, 2));

        const float mn0 = fmaxf(m[0], ml0), mn1 = fmaxf(m[1], ml1);
        const float a0 = exp2f(m[0] - mn0), a1 = exp2f(m[1] - mn1);
        m[0] = mn0; m[1] = mn1;

        float ll0 = 0.0f, ll1 = 0.0f;
#pragma unroll
        for (int nt = 0; nt < 8; nt++) {
            sc[nt][0] = exp2f(sc[nt][0] - mn0);
            sc[nt][1] = exp2f(sc[nt][1] - mn0);
            sc[nt][2] = exp2f(sc[nt][2] - mn1);
            sc[nt][3] = exp2f(sc[nt][3] - mn1);
            ll0 += sc[nt][0] + sc[nt][1];
            ll1 += sc[nt][2] + sc[nt][3];
        }
        ll0 += __shfl_xor_sync(0xffffffffu, ll0, 1);
        ll0 += __shfl_xor_sync(0xffffffffu, ll0, 2);
        ll1 += __shfl_xor_sync(0xffffffffu, ll1, 1);
        ll1 += __shfl_xor_sync(0xffffffffu, ll1, 2);
        l[0] = l[0] * a0 + ll0;
        l[1] = l[1] * a1 + ll1;

#pragma unroll
        for (int nt = 0; nt < 8; nt++) {
            of[nt][0] *= a0; of[nt][1] *= a0;
            of[nt][2] *= a1; of[nt][3] *= a1;
        }

        // ---- P -> warp-private smem (RNA), reload as A-fragments ----
        {
            const uint32_t r0a = pw + (uint32_t)((lane >> 2) * ARB + 2 * (lane & 3) * 4);
#pragma unroll
            for (int nt = 0; nt < 8; nt++) {
                float2 v0 = make_float2(tf32_rna(sc[nt][0]), tf32_rna(sc[nt][1]));
                float2 v1 = make_float2(tf32_rna(sc[nt][2]), tf32_rna(sc[nt][3]));
                asm volatile("st.shared.v2.f32 [%0], {%1, %2};"
                             :: "r"(r0a + nt * 32), "f"(v0.x), "f"(v0.y));
                asm volatile("st.shared.v2.f32 [%0], {%1, %2};"
                             :: "r"(r0a + 8 * ARB + nt * 32), "f"(v1.x), "f"(v1.y));
            }
        }
        __syncwarp();

        // ---- O += P V ----
#pragma unroll
        for (int kc = 0; kc < 8; kc++) {
            uint32_t af[4];
            ldsm_x4(af[0], af[1], af[2], af[3],
                    pw + (uint32_t)(a_row * ARB + (kc * 8 + a_co) * 4));
#pragma unroll
            for (int p = 0; p < 4; p++) {
                uint32_t r0, r1, r2, r3;
                ldsm_x4(r0, r1, r2, r3,
                        vbase + (uint32_t)((p * 16 + b_row) * ARB + (kc * 8 + b_co) * 4));
                uint32_t b0[2] = {r0, r1}, b1[2] = {r2, r3};
                mma_tf32(of[2 * p],     af, b0);
                mma_tf32(of[2 * p + 1], af, b1);
            }
        }

        if (++buf == 3) buf = 0;
    }

    // ---- epilogue ----
    const float inv0 = 1.0f / l[0], inv1 = 1.0f / l[1];
    const int b = bh >> 4, h = bh & 15;
    const int s0 = qb * 128 + w * 16 + (lane >> 2);
#pragma unroll
    for (int nt = 0; nt < 8; nt++) {
        int n = h * 64 + nt * 8 + 2 * (lane & 3);
        float2 v0, v1;
        v0.x = tf32_rna(of[nt][0] * inv0);
        v0.y = tf32_rna(of[nt][1] * inv0);
        v1.x = tf32_rna(of[nt][2] * inv1);
        v1.y = tf32_rna(of[nt][3] * inv1);
        *(float2*)&g_AO[(size_t)(b * Ssz + s0) * Dsz + n]       = v0;
        *(float2*)&g_AO[(size_t)(b * Ssz + s0 + 8) * Dsz + n]   = v1;
    }
}

// ===========================================================================
extern "C" void kernel_launch(void* const* d_in, const int* in_sizes, int n_in,
                              void* d_out, int out_size)
{
    const float* X  = (const float*)d_in[0];
    const float* Wq = (const float*)d_in[1];
    const float* Wk = (const float*)d_in[2];
    const float* Wv = (const float*)d_in[3];
    const float* Wo = (const float*)d_in[4];
    float* Out = (float*)d_out;

    cudaFuncSetAttribute(qkv_mma_kernel,
                         cudaFuncAttributeMaxDynamicSharedMemorySize, GSMEM);
    cudaFuncSetAttribute(out_mma_kernel,
                         cudaFuncAttributeMaxDynamicSharedMemorySize, GSMEM);
    cudaFuncSetAttribute(attn_mma_kernel,
                         cudaFuncAttributeMaxDynamicSharedMemorySize, ASMEM);

    round_all_kernel<<<(XN + 4 * WN) / 1024, 256>>>(X, Wq, Wk, Wv, Wo);

    dim3 gq(8, 64, 3);
    qkv_mma_kernel<<<gq, 256, GSMEM>>>();

    dim3 gt(64, 2, 64);
    vt_kernel<<<gt, dim3(32, 8)>>>();

    dim3 ga(16, 64);
    attn_mma_kernel<<<ga, 256, ASMEM>>>();

    dim3 go(8, 64);
    out_mma_kernel<<<go, 256, GSMEM>>>(Out);
}

// round 10
// speedup vs baseline: 3.7223x; 1.0644x over previous
#include <cuda_runtime.h>
#include <math.h>
#include <stdint.h>

#define Bsz  4
#define Ssz  2048
#define Dsz  1024
#define Hsz  16
#define HDsz 64
#define Msz  (Bsz * Ssz)   // 8192

// Scratch (device globals: allocation-free rule)
__device__ float g_Q[Msz * Dsz];    // [B,H,S,hd] (tf32-rounded, scaled log2e/8)
__device__ float g_K[Msz * Dsz];    // [B,H,S,hd] (tf32-rounded)
__device__ float g_Vt[Msz * Dsz];   // [B,H,hd,S] transposed V (tf32-rounded)
__device__ float g_AO[Msz * Dsz];   // [B,S,H*hd], tf32-rounded
__device__ float g_Xr[Msz * Dsz];   // X rounded to tf32 (RNA)
__device__ float g_Wq[Dsz * Dsz];
__device__ float g_Wk[Dsz * Dsz];
__device__ float g_Wv[Dsz * Dsz];
__device__ float g_Wo[Dsz * Dsz];

// ===========================================================================
// helpers
// ===========================================================================
__device__ __forceinline__ uint32_t smem_u32(const void* p) {
    uint32_t a;
    asm("{ .reg .u64 t; cvta.to.shared.u64 t, %1; cvt.u32.u64 %0, t; }"
        : "=r"(a) : "l"(p));
    return a;
}
__device__ __forceinline__ float tf32_rna(float x) {
    uint32_t u;
    asm("cvt.rna.tf32.f32 %0, %1;" : "=r"(u) : "f"(x));
    return __uint_as_float(u);
}
__device__ __forceinline__ void ldsm_x4(uint32_t& r0, uint32_t& r1,
                                        uint32_t& r2, uint32_t& r3, uint32_t a) {
    asm volatile("ldmatrix.sync.aligned.m8n8.x4.shared.b16 {%0,%1,%2,%3}, [%4];"
                 : "=r"(r0), "=r"(r1), "=r"(r2), "=r"(r3) : "r"(a));
}
__device__ __forceinline__ void mma_tf32(float* c, const uint32_t* a,
                                         const uint32_t* b) {
    asm volatile(
        "mma.sync.aligned.m16n8k8.row.col.f32.tf32.tf32.f32 "
        "{%0,%1,%2,%3}, {%4,%5,%6,%7}, {%8,%9}, {%0,%1,%2,%3};"
        : "+f"(c[0]), "+f"(c[1]), "+f"(c[2]), "+f"(c[3])
        : "r"(a[0]), "r"(a[1]), "r"(a[2]), "r"(a[3]), "r"(b[0]), "r"(b[1]));
}
__device__ __forceinline__ void cp16(uint32_t saddr, const void* gaddr) {
    asm volatile("cp.async.cg.shared.global [%0], [%1], 16;"
                 :: "r"(saddr), "l"(gaddr));
}

// ===========================================================================
// tf32 mma.sync GEMM: D[128,128] = A[bm:,1024] * W[bn:,1024]^T  (NT)
// 2-stage cp.async pipeline, 2 CTAs/SM.
// ===========================================================================
#define BK        32
#define ROWPAD    36
#define ATILE_B   (128 * ROWPAD * 4)        // 18432
#define STAGE_B   (2 * ATILE_B)             // 36864
#define GSMEM     (2 * STAGE_B)             // 73728

struct CFrag { float c[4][4][4]; };

__device__ __forceinline__ void tf32_gemm_main(const float* __restrict__ A,
                                               const float* __restrict__ W,
                                               int bm, int bn, char* smem,
                                               CFrag& C)
{
    const int tid  = threadIdx.x;
    const int wid  = tid >> 5;
    const int lane = tid & 31;
    const int wm   = (wid & 1) * 64;
    const int wn   = (wid >> 1) * 32;
    const uint32_t sbase = smem_u32(smem);

#pragma unroll
    for (int i = 0; i < 4; i++)
#pragma unroll
        for (int j = 0; j < 4; j++)
#pragma unroll
            for (int q = 0; q < 4; q++) C.c[i][j][q] = 0.0f;

    auto load_stage = [&](int st, int k0) {
        const uint32_t sb = sbase + st * STAGE_B;
#pragma unroll
        for (int i = 0; i < 4; i++) {
            int id  = tid + i * 256;
            int row = id >> 3;
            int ch  = id & 7;
            uint32_t so = (uint32_t)(row * 144 + ch * 16);
            cp16(sb + so,            A + (size_t)(bm + row) * 1024 + k0 + ch * 4);
            cp16(sb + ATILE_B + so,  W + (size_t)(bn + row) * 1024 + k0 + ch * 4);
        }
        asm volatile("cp.async.commit_group;" ::: "memory");
    };

    load_stage(0, 0);
    load_stage(1, BK);

    const int a_row = (lane & 7) + ((lane >> 3) & 1) * 8;
    const int a_co  = (lane >> 4) * 4;
    const int b_row = (lane & 7) + (lane >> 4) * 8;
    const int b_co  = ((lane >> 3) & 1) * 4;

    for (int k = 0; k < 32; k++) {
        const int st = k & 1;
        if (k < 31) asm volatile("cp.async.wait_group 1;" ::: "memory");
        else        asm volatile("cp.async.wait_group 0;" ::: "memory");
        __syncthreads();

        const uint32_t sa = sbase + st * STAGE_B;
        const uint32_t sw = sa + ATILE_B;
#pragma unroll
        for (int s8 = 0; s8 < 4; s8++) {
            const int k0 = s8 * 8;
            uint32_t a[4][4], b[4][2];
#pragma unroll
            for (int mt = 0; mt < 4; mt++) {
                int r = wm + mt * 16 + a_row;
                ldsm_x4(a[mt][0], a[mt][1], a[mt][2], a[mt][3],
                        sa + (uint32_t)(r * 144 + (k0 + a_co) * 4));
            }
#pragma unroll
            for (int p = 0; p < 2; p++) {
                int n = wn + p * 16 + b_row;
                uint32_t r0, r1, r2, r3;
                ldsm_x4(r0, r1, r2, r3,
                        sw + (uint32_t)(n * 144 + (k0 + b_co) * 4));
                b[2 * p][0] = r0;  b[2 * p][1] = r1;
                b[2 * p + 1][0] = r2;  b[2 * p + 1][1] = r3;
            }
#pragma unroll
            for (int mt = 0; mt < 4; mt++)
#pragma unroll
                for (int nt = 0; nt < 4; nt++)
                    mma_tf32(C.c[mt][nt], a[mt], b[nt]);
        }

        __syncthreads();
        if (k + 2 < 32) load_stage((k + 2) & 1, (k + 2) * BK);
    }
}

// ===========================================================================
// QKV projection: grid (8, 64, 3). Outputs RNA-rounded tf32.
// z==0: Q scaled by log2(e)/8 (exp2-domain softmax).
// z==2: V written DIRECTLY TRANSPOSED into g_Vt[bh][d][s].
// ===========================================================================
#define QSCALE 0.18033688011112042f    // log2(e) / 8

__global__ __launch_bounds__(256, 2)
void qkv_mma_kernel()
{
    extern __shared__ char smem[];
    const int bn = blockIdx.x * 128;
    const int bm = blockIdx.y * 128;
    const int z  = blockIdx.z;
    const float* W = (z == 0) ? g_Wq : (z == 1) ? g_Wk : g_Wv;

    CFrag C;
    tf32_gemm_main(g_Xr, W, bm, bn, smem, C);

    const int wid  = threadIdx.x >> 5;
    const int lane = threadIdx.x & 31;
    const int wm = (wid & 1) * 64, wn = (wid >> 1) * 32;

    if (z == 2) {
        // V: transposed store into g_Vt[bh][d][s]
#pragma unroll
        for (int mt = 0; mt < 4; mt++) {
#pragma unroll
            for (int nt = 0; nt < 4; nt++) {
                int n = bn + wn + nt * 8 + 2 * (lane & 3);
                int h = n >> 6, d = n & 63;
#pragma unroll
                for (int half = 0; half < 2; half++) {
                    int m = bm + wm + mt * 16 + (lane >> 2) + half * 8;
                    int b = m >> 11, s = m & 2047;
                    float* base =
                        &g_Vt[((size_t)(b * Hsz + h) * HDsz + d) * Ssz + s];
                    base[0]   = tf32_rna(C.c[mt][nt][2 * half + 0]);
                    base[Ssz] = tf32_rna(C.c[mt][nt][2 * half + 1]);
                }
            }
        }
    } else {
        float* Dst = (z == 0) ? g_Q : g_K;
        const float scale = (z == 0) ? QSCALE : 1.0f;
#pragma unroll
        for (int mt = 0; mt < 4; mt++) {
#pragma unroll
            for (int nt = 0; nt < 4; nt++) {
                int n = bn + wn + nt * 8 + 2 * (lane & 3);
                int h = n >> 6, d = n & 63;
#pragma unroll
                for (int half = 0; half < 2; half++) {
                    int m = bm + wm + mt * 16 + (lane >> 2) + half * 8;
                    int b = m >> 11, s = m & 2047;
                    float* p =
                        &Dst[(((size_t)(b * Hsz + h)) * Ssz + s) * HDsz + d];
                    float2 v;
                    v.x = tf32_rna(C.c[mt][nt][2 * half + 0] * scale);
                    v.y = tf32_rna(C.c[mt][nt][2 * half + 1] * scale);
                    *(float2*)p = v;
                }
            }
        }
    }
}

// ===========================================================================
// Output projection: grid (8, 64) -> d_out
// ===========================================================================
__global__ __launch_bounds__(256, 2)
void out_mma_kernel(float* __restrict__ Out)
{
    extern __shared__ char smem[];
    const int bn = blockIdx.x * 128;
    const int bm = blockIdx.y * 128;

    CFrag C;
    tf32_gemm_main(g_AO, g_Wo, bm, bn, smem, C);

    const int wid  = threadIdx.x >> 5;
    const int lane = threadIdx.x & 31;
    const int wm = (wid & 1) * 64, wn = (wid >> 1) * 32;

#pragma unroll
    for (int mt = 0; mt < 4; mt++) {
#pragma unroll
        for (int nt = 0; nt < 4; nt++) {
            int n = bn + wn + nt * 8 + 2 * (lane & 3);
#pragma unroll
            for (int half = 0; half < 2; half++) {
                int m = bm + wm + mt * 16 + (lane >> 2) + half * 8;
                float2 v;
                v.x = C.c[mt][nt][2 * half + 0];
                v.y = C.c[mt][nt][2 * half + 1];
                *(float2*)&Out[(size_t)m * 1024 + n] = v;
            }
        }
    }
}

// ===========================================================================
// Merged RNA-rounding: X (8M) then Wq/Wk/Wv/Wo (1M each), one launch.
// ===========================================================================
#define XN (Msz * Dsz)        // 8388608
#define WN (Dsz * Dsz)        // 1048576

__global__ __launch_bounds__(256)
void round_all_kernel(const float* __restrict__ X,  const float* __restrict__ Wq,
                      const float* __restrict__ Wk, const float* __restrict__ Wv,
                      const float* __restrict__ Wo)
{
    int i = (blockIdx.x * 256 + threadIdx.x) * 4;
    const float* src;
    float* dst;
    if (i < XN)               { src = X  + i;               dst = g_Xr + i; }
    else if (i < XN + WN)     { src = Wq + (i - XN);        dst = g_Wq + (i - XN); }
    else if (i < XN + 2 * WN) { src = Wk + (i - XN - WN);   dst = g_Wk + (i - XN - WN); }
    else if (i < XN + 3 * WN) { src = Wv + (i - XN - 2*WN); dst = g_Wv + (i - XN - 2*WN); }
    else                      { src = Wo + (i - XN - 3*WN); dst = g_Wo + (i - XN - 3*WN); }
    float4 v = *(const float4*)src;
    v.x = tf32_rna(v.x); v.y = tf32_rna(v.y);
    v.z = tf32_rna(v.z); v.w = tf32_rna(v.w);
    *(float4*)dst = v;
}

// ===========================================================================
// Flash attention, tf32 mma.sync.
// grid (32, 64), 128 threads = 4 warps, TWO CTAs per SM (desync barrier
// domains hide softmax/barrier latency of the other CTA).
// CTA: 64 q rows; warp: 16 q rows. KV blocks of 64, double-buffered cp.async.
// ===========================================================================
#define ARS   68
#define ARB   272
#define KVT_B (64 * ARB)                   // 17408
#define ASMEM (4 * KVT_B + 64 * ARB)       // 87040

__global__ __launch_bounds__(128, 2)
void attn_mma_kernel()
{
    extern __shared__ float sm[];
    float* sP = sm + 4 * 64 * ARS;         // [64][68], also Q staging

    const int tid = threadIdx.x;
    const int w   = tid >> 5;
    const int lane = tid & 31;
    const int qb = blockIdx.x;
    const int bh = blockIdx.y;

    const float* Qp  = g_Q  + (size_t)bh * (Ssz * HDsz) + (size_t)qb * 64 * HDsz;
    const float* Kp  = g_K  + (size_t)bh * (Ssz * HDsz);
    const float* Vtp = g_Vt + (size_t)bh * (HDsz * Ssz);

    const uint32_t sKb = smem_u32(sm);
    const uint32_t sVb = sKb + 2 * KVT_B;
    const uint32_t sPb = sKb + 4 * KVT_B;

    // ---- stage Q (64 rows), build persistent A-fragments ----
#pragma unroll
    for (int i = 0; i < 8; i++) {
        int id = tid + i * 128;            // 0..1023
        int r = id >> 4, ch = id & 15;
        *(float4*)&sP[r * ARS + ch * 4] = *(const float4*)&Qp[r * 64 + ch * 4];
    }
    __syncthreads();

    const int a_row = (lane & 7) + ((lane >> 3) & 1) * 8;
    const int a_co  = (lane >> 4) * 4;
    const int b_row = (lane & 7) + (lane >> 4) * 8;
    const int b_co  = ((lane >> 3) & 1) * 4;

    uint32_t qf[8][4];
#pragma unroll
    for (int kc = 0; kc < 8; kc++)
        ldsm_x4(qf[kc][0], qf[kc][1], qf[kc][2], qf[kc][3],
                sPb + (uint32_t)((w * 16 + a_row) * ARB + (kc * 8 + a_co) * 4));
    __syncthreads();

    auto load_kv = [&](int kb, int buf) {
        const float* kg = Kp  + (size_t)kb * 64 * 64;
        const float* vg = Vtp + kb * 64;
        const uint32_t kd = sKb + buf * KVT_B;
        const uint32_t vd = sVb + buf * KVT_B;
#pragma unroll
        for (int i = 0; i < 8; i++) {
            int id = tid + i * 128;        // 0..1023
            int r = id >> 4, ch = id & 15;
            cp16(kd + r * ARB + ch * 16, kg + r * 64 + ch * 4);
            cp16(vd + r * ARB + ch * 16, vg + (size_t)r * Ssz + ch * 4);
        }
        asm volatile("cp.async.commit_group;" ::: "memory");
    };

    load_kv(0, 0);
    load_kv(1, 1);

    float m[2] = {-1e30f, -1e30f}, l[2] = {0.0f, 0.0f};
    float of[8][4];
#pragma unroll
    for (int nt = 0; nt < 8; nt++)
#pragma unroll
        for (int q = 0; q < 4; q++) of[nt][q] = 0.0f;

    const uint32_t pw = sPb + (uint32_t)(w * 16) * ARB;

    for (int kb = 0; kb < 32; kb++) {
        const int buf = kb & 1;
        // pending groups at top: {kb, kb+1}
        if (kb < 31) asm volatile("cp.async.wait_group 1;" ::: "memory");
        else         asm volatile("cp.async.wait_group 0;" ::: "memory");
        __syncthreads();

        const uint32_t kbase = sKb + buf * KVT_B;
        const uint32_t vbase = sVb + buf * KVT_B;

        // ---- S = Q K^T (log2 domain) ----
        float sc[8][4];
#pragma unroll
        for (int nt = 0; nt < 8; nt++)
#pragma unroll
            for (int q = 0; q < 4; q++) sc[nt][q] = 0.0f;

#pragma unroll
        for (int kc = 0; kc < 8; kc++) {
#pragma unroll
            for (int p = 0; p < 4; p++) {
                uint32_t r0, r1, r2, r3;
                ldsm_x4(r0, r1, r2, r3,
                        kbase + (uint32_t)((p * 16 + b_row) * ARB + (kc * 8 + b_co) * 4));
                uint32_t b0[2] = {r0, r1}, b1[2] = {r2, r3};
                mma_tf32(sc[2 * p],     qf[kc], b0);
                mma_tf32(sc[2 * p + 1], qf[kc], b1);
            }
        }

        // ---- online softmax in exp2 domain ----
        float ml0 = -1e30f, ml1 = -1e30f;
#pragma unroll
        for (int nt = 0; nt < 8; nt++) {
            ml0 = fmaxf(ml0, fmaxf(sc[nt][0], sc[nt][1]));
            ml1 = fmaxf(ml1, fmaxf(sc[nt][2], sc[nt][3]));
        }
        ml0 = fmaxf(ml0, __shfl_xor_sync(0xffffffffu, ml0, 1));
        ml0 = fmaxf(ml0, __shfl_xor_sync(0xffffffffu, ml0, 2));
        ml1 = fmaxf(ml1, __shfl_xor_sync(0xffffffffu, ml1, 1));
        ml1 = fmaxf(ml1, __shfl_xor_sync(0xffffffffu, ml1, 2));

        const float mn0 = fmaxf(m[0], ml0), mn1 = fmaxf(m[1], ml1);
        const float a0 = exp2f(m[0] - mn0), a1 = exp2f(m[1] - mn1);
        m[0] = mn0; m[1] = mn1;

        float ll0 = 0.0f, ll1 = 0.0f;
#pragma unroll
        for (int nt = 0; nt < 8; nt++) {
            sc[nt][0] = exp2f(sc[nt][0] - mn0);
            sc[nt][1] = exp2f(sc[nt][1] - mn0);
            sc[nt][2] = exp2f(sc[nt][2] - mn1);
            sc[nt][3] = exp2f(sc[nt][3] - mn1);
            ll0 += sc[nt][0] + sc[nt][1];
            ll1 += sc[nt][2] + sc[nt][3];
        }
        ll0 += __shfl_xor_sync(0xffffffffu, ll0, 1);
        ll0 += __shfl_xor_sync(0xffffffffu, ll0, 2);
        ll1 += __shfl_xor_sync(0xffffffffu, ll1, 1);
        ll1 += __shfl_xor_sync(0xffffffffu, ll1, 2);
        l[0] = l[0] * a0 + ll0;
        l[1] = l[1] * a1 + ll1;

#pragma unroll
        for (int nt = 0; nt < 8; nt++) {
            of[nt][0] *= a0; of[nt][1] *= a0;
            of[nt][2] *= a1; of[nt][3] *= a1;
        }

        // ---- P -> warp-private smem (RNA), reload as A-fragments ----
        {
            const uint32_t r0a = pw + (uint32_t)((lane >> 2) * ARB + 2 * (lane & 3) * 4);
#pragma unroll
            for (int nt = 0; nt < 8; nt++) {
                float2 v0 = make_float2(tf32_rna(sc[nt][0]), tf32_rna(sc[nt][1]));
                float2 v1 = make_float2(tf32_rna(sc[nt][2]), tf32_rna(sc[nt][3]));
                asm volatile("st.shared.v2.f32 [%0], {%1, %2};"
                             :: "r"(r0a + nt * 32), "f"(v0.x), "f"(v0.y));
                asm volatile("st.shared.v2.f32 [%0], {%1, %2};"
                             :: "r"(r0a + 8 * ARB + nt * 32), "f"(v1.x), "f"(v1.y));
            }
        }
        __syncwarp();

        // ---- O += P V ----
#pragma unroll
        for (int kc = 0; kc < 8; kc++) {
            uint32_t af[4];
            ldsm_x4(af[0], af[1], af[2], af[3],
                    pw + (uint32_t)(a_row * ARB + (kc * 8 + a_co) * 4));
#pragma unroll
            for (int p = 0; p < 4; p++) {
                uint32_t r0, r1, r2, r3;
                ldsm_x4(r0, r1, r2, r3,
                        vbase + (uint32_t)((p * 16 + b_row) * ARB + (kc * 8 + b_co) * 4));
                uint32_t b0[2] = {r0, r1}, b1[2] = {r2, r3};
                mma_tf32(of[2 * p],     af, b0);
                mma_tf32(of[2 * p + 1], af, b1);
            }
        }

        __syncthreads();                   // readers done with buf
        if (kb + 2 < 32) load_kv(kb + 2, buf);
    }

    // ---- epilogue ----
    const float inv0 = 1.0f / l[0], inv1 = 1.0f / l[1];
    const int b = bh >> 4, h = bh & 15;
    const int s0 = qb * 64 + w * 16 + (lane >> 2);
#pragma unroll
    for (int nt = 0; nt < 8; nt++) {
        int n = h * 64 + nt * 8 + 2 * (lane & 3);
        float2 v0, v1;
        v0.x = tf32_rna(of[nt][0] * inv0);
        v0.y = tf32_rna(of[nt][1] * inv0);
        v1.x = tf32_rna(of[nt][2] * inv1);
        v1.y = tf32_rna(of[nt][3] * inv1);
        *(float2*)&g_AO[(size_t)(b * Ssz + s0) * Dsz + n]       = v0;
        *(float2*)&g_AO[(size_t)(b * Ssz + s0 + 8) * Dsz + n]   = v1;
    }
}

// ===========================================================================
extern "C" void kernel_launch(void* const* d_in, const int* in_sizes, int n_in,
                              void* d_out, int out_size)
{
    const float* X  = (const float*)d_in[0];
    const float* Wq = (const float*)d_in[1];
    const float* Wk = (const float*)d_in[2];
    const float* Wv = (const float*)d_in[3];
    const float* Wo = (const float*)d_in[4];
    float* Out = (float*)d_out;

    cudaFuncSetAttribute(qkv_mma_kernel,
                         cudaFuncAttributeMaxDynamicSharedMemorySize, GSMEM);
    cudaFuncSetAttribute(out_mma_kernel,
                         cudaFuncAttributeMaxDynamicSharedMemorySize, GSMEM);
    cudaFuncSetAttribute(attn_mma_kernel,
                         cudaFuncAttributeMaxDynamicSharedMemorySize, ASMEM);

    round_all_kernel<<<(XN + 4 * WN) / 1024, 256>>>(X, Wq, Wk, Wv, Wo);

    dim3 gq(8, 64, 3);
    qkv_mma_kernel<<<gq, 256, GSMEM>>>();

    dim3 ga(32, 64);
    attn_mma_kernel<<<ga, 128, ASMEM>>>();

    dim3 go(8, 64);
    out_mma_kernel<<<go, 256, GSMEM>>>(Out);
}

// round 13
// speedup vs baseline: 3.7726x; 1.0135x over previous
#include <cuda_runtime.h>
#include <math.h>
#include <stdint.h>

#define Bsz  4
#define Ssz  2048
#define Dsz  1024
#define Hsz  16
#define HDsz 64
#define Msz  (Bsz * Ssz)   // 8192

// Scratch (device globals: allocation-free rule)
__device__ float g_Q[Msz * Dsz];    // [B,H,S,hd] (tf32-rounded, scaled log2e/8)
__device__ float g_K[Msz * Dsz];    // [B,H,S,hd] (tf32-rounded)
__device__ float g_Vt[Msz * Dsz];   // [B,H,hd,S] transposed V (tf32-rounded)
__device__ float g_AO[Msz * Dsz];   // [B,S,H*hd], tf32-rounded
__device__ float g_Xr[Msz * Dsz];   // X rounded to tf32 (RNA)
__device__ float g_Wq[Dsz * Dsz];
__device__ float g_Wk[Dsz * Dsz];
__device__ float g_Wv[Dsz * Dsz];
__device__ float g_Wo[Dsz * Dsz];

// ===========================================================================
// helpers
// ===========================================================================
__device__ __forceinline__ uint32_t smem_u32(const void* p) {
    uint32_t a;
    asm("{ .reg .u64 t; cvta.to.shared.u64 t, %1; cvt.u32.u64 %0, t; }"
        : "=r"(a) : "l"(p));
    return a;
}
__device__ __forceinline__ float tf32_rna(float x) {
    uint32_t u;
    asm("cvt.rna.tf32.f32 %0, %1;" : "=r"(u) : "f"(x));
    return __uint_as_float(u);
}
__device__ __forceinline__ void ldsm_x4(uint32_t& r0, uint32_t& r1,
                                        uint32_t& r2, uint32_t& r3, uint32_t a) {
    asm volatile("ldmatrix.sync.aligned.m8n8.x4.shared.b16 {%0,%1,%2,%3}, [%4];"
                 : "=r"(r0), "=r"(r1), "=r"(r2), "=r"(r3) : "r"(a));
}
__device__ __forceinline__ void mma_tf32(float* c, const uint32_t* a,
                                         const uint32_t* b) {
    asm volatile(
        "mma.sync.aligned.m16n8k8.row.col.f32.tf32.tf32.f32 "
        "{%0,%1,%2,%3}, {%4,%5,%6,%7}, {%8,%9}, {%0,%1,%2,%3};"
        : "+f"(c[0]), "+f"(c[1]), "+f"(c[2]), "+f"(c[3])
        : "r"(a[0]), "r"(a[1]), "r"(a[2]), "r"(a[3]), "r"(b[0]), "r"(b[1]));
}
__device__ __forceinline__ void cp16(uint32_t saddr, const void* gaddr) {
    asm volatile("cp.async.cg.shared.global [%0], [%1], 16;"
                 :: "r"(saddr), "l"(gaddr));
}

// ===========================================================================
// tf32 mma.sync GEMM: D[128,128] = A[bm:,1024] * W[bn:,1024]^T  (NT)
// 3-stage cp.async ring, ONE syncthreads/iter, refill-before-compute.
// 2 CTAs/SM (3 * 36864 = 110592 B/CTA).
// ===========================================================================
#define BK        32
#define ROWPAD    36
#define ATILE_B   (128 * ROWPAD * 4)        // 18432
#define STAGE_B   (2 * ATILE_B)             // 36864
#define GSMEM     (3 * STAGE_B)             // 110592

struct CFrag { float c[4][4][4]; };

__device__ __forceinline__ void tf32_gemm_main(const float* __restrict__ A,
                                               const float* __restrict__ W,
                                               int bm, int bn, char* smem,
                                               CFrag& C)
{
    const int tid  = threadIdx.x;
    const int wid  = tid >> 5;
    const int lane = tid & 31;
    const int wm   = (wid & 1) * 64;
    const int wn   = (wid >> 1) * 32;
    const uint32_t sbase = smem_u32(smem);

#pragma unroll
    for (int i = 0; i < 4; i++)
#pragma unroll
        for (int j = 0; j < 4; j++)
#pragma unroll
            for (int q = 0; q < 4; q++) C.c[i][j][q] = 0.0f;

    auto load_stage = [&](int st, int k0) {
        const uint32_t sb = sbase + st * STAGE_B;
#pragma unroll
        for (int i = 0; i < 4; i++) {
            int id  = tid + i * 256;
            int row = id >> 3;
            int ch  = id & 7;
            uint32_t so = (uint32_t)(row * 144 + ch * 16);
            cp16(sb + so,            A + (size_t)(bm + row) * 1024 + k0 + ch * 4);
            cp16(sb + ATILE_B + so,  W + (size_t)(bn + row) * 1024 + k0 + ch * 4);
        }
        asm volatile("cp.async.commit_group;" ::: "memory");
    };

    load_stage(0, 0);
    load_stage(1, BK);

    const int a_row = (lane & 7) + ((lane >> 3) & 1) * 8;
    const int a_co  = (lane >> 4) * 4;
    const int b_row = (lane & 7) + (lane >> 4) * 8;
    const int b_co  = ((lane >> 3) & 1) * 4;

    int st = 0;
    for (int k = 0; k < 32; k++) {
        // pending groups at top: {k, k+1}
        if (k < 31) asm volatile("cp.async.wait_group 1;" ::: "memory");
        else        asm volatile("cp.async.wait_group 0;" ::: "memory");
        __syncthreads();       // slot k visible; readers of slot (k+2)%3 done (iter k-1)
        if (k + 2 < 32) {
            int nb = st + 2; if (nb >= 3) nb -= 3;
            load_stage(nb, (k + 2) * BK);   // overlaps this iteration's compute
        }

        const uint32_t sa = sbase + st * STAGE_B;
        const uint32_t sw = sa + ATILE_B;
#pragma unroll
        for (int s8 = 0; s8 < 4; s8++) {
            const int k0 = s8 * 8;
            uint32_t a[4][4], b[4][2];
#pragma unroll
            for (int mt = 0; mt < 4; mt++) {
                int r = wm + mt * 16 + a_row;
                ldsm_x4(a[mt][0], a[mt][1], a[mt][2], a[mt][3],
                        sa + (uint32_t)(r * 144 + (k0 + a_co) * 4));
            }
#pragma unroll
            for (int p = 0; p < 2; p++) {
                int n = wn + p * 16 + b_row;
                uint32_t r0, r1, r2, r3;
                ldsm_x4(r0, r1, r2, r3,
                        sw + (uint32_t)(n * 144 + (k0 + b_co) * 4));
                b[2 * p][0] = r0;  b[2 * p][1] = r1;
                b[2 * p + 1][0] = r2;  b[2 * p + 1][1] = r3;
            }
#pragma unroll
            for (int mt = 0; mt < 4; mt++)
#pragma unroll
                for (int nt = 0; nt < 4; nt++)
                    mma_tf32(C.c[mt][nt], a[mt], b[nt]);
        }

        if (++st == 3) st = 0;
    }
}

// ===========================================================================
// QKV projection: grid (8, 64, 3). Outputs RNA-rounded tf32.
// z==0: Q scaled by log2(e)/8 (exp2-domain softmax).
// z==2: V written DIRECTLY TRANSPOSED into g_Vt[bh][d][s].
// ===========================================================================
#define QSCALE 0.18033688011112042f    // log2(e) / 8

__global__ __launch_bounds__(256, 2)
void qkv_mma_kernel()
{
    extern __shared__ char smem[];
    const int bn = blockIdx.x * 128;
    const int bm = blockIdx.y * 128;
    const int z  = blockIdx.z;
    const float* W = (z == 0) ? g_Wq : (z == 1) ? g_Wk : g_Wv;

    CFrag C;
    tf32_gemm_main(g_Xr, W, bm, bn, smem, C);

    const int wid  = threadIdx.x >> 5;
    const int lane = threadIdx.x & 31;
    const int wm = (wid & 1) * 64, wn = (wid >> 1) * 32;

    if (z == 2) {
        // V: transposed store into g_Vt[bh][d][s]
#pragma unroll
        for (int mt = 0; mt < 4; mt++) {
#pragma unroll
            for (int nt = 0; nt < 4; nt++) {
                int n = bn + wn + nt * 8 + 2 * (lane & 3);
                int h = n >> 6, d = n & 63;
#pragma unroll
                for (int half = 0; half < 2; half++) {
                    int m = bm + wm + mt * 16 + (lane >> 2) + half * 8;
                    int b = m >> 11, s = m & 2047;
                    float* base =
                        &g_Vt[((size_t)(b * Hsz + h) * HDsz + d) * Ssz + s];
                    base[0]   = tf32_rna(C.c[mt][nt][2 * half + 0]);
                    base[Ssz] = tf32_rna(C.c[mt][nt][2 * half + 1]);
                }
            }
        }
    } else {
        float* Dst = (z == 0) ? g_Q : g_K;
        const float scale = (z == 0) ? QSCALE : 1.0f;
#pragma unroll
        for (int mt = 0; mt < 4; mt++) {
#pragma unroll
            for (int nt = 0; nt < 4; nt++) {
                int n = bn + wn + nt * 8 + 2 * (lane & 3);
                int h = n >> 6, d = n & 63;
#pragma unroll
                for (int half = 0; half < 2; half++) {
                    int m = bm + wm + mt * 16 + (lane >> 2) + half * 8;
                    int b = m >> 11, s = m & 2047;
                    float* p =
                        &Dst[(((size_t)(b * Hsz + h)) * Ssz + s) * HDsz + d];
                    float2 v;
                    v.x = tf32_rna(C.c[mt][nt][2 * half + 0] * scale);
                    v.y = tf32_rna(C.c[mt][nt][2 * half + 1] * scale);
                    *(float2*)p = v;
                }
            }
        }
    }
}

// ===========================================================================
// Output projection: grid (8, 64) -> d_out
// ===========================================================================
__global__ __launch_bounds__(256, 2)
void out_mma_kernel(float* __restrict__ Out)
{
    extern __shared__ char smem[];
    const int bn = blockIdx.x * 128;
    const int bm = blockIdx.y * 128;

    CFrag C;
    tf32_gemm_main(g_AO, g_Wo, bm, bn, smem, C);

    const int wid  = threadIdx.x >> 5;
    const int lane = threadIdx.x & 31;
    const int wm = (wid & 1) * 64, wn = (wid >> 1) * 32;

#pragma unroll
    for (int mt = 0; mt < 4; mt++) {
#pragma unroll
        for (int nt = 0; nt < 4; nt++) {
            int n = bn + wn + nt * 8 + 2 * (lane & 3);
#pragma unroll
            for (int half = 0; half < 2; half++) {
                int m = bm + wm + mt * 16 + (lane >> 2) + half * 8;
                float2 v;
                v.x = C.c[mt][nt][2 * half + 0];
                v.y = C.c[mt][nt][2 * half + 1];
                *(float2*)&Out[(size_t)m * 1024 + n] = v;
            }
        }
    }
}

// ===========================================================================
// Merged RNA-rounding: X (8M) then Wq/Wk/Wv/Wo (1M each), one launch.
// ===========================================================================
#define XN (Msz * Dsz)        // 8388608
#define WN (Dsz * Dsz)        // 1048576

__global__ __launch_bounds__(256)
void round_all_kernel(const float* __restrict__ X,  const float* __restrict__ Wq,
                      const float* __restrict__ Wk, const float* __restrict__ Wv,
                      const float* __restrict__ Wo)
{
    int i = (blockIdx.x * 256 + threadIdx.x) * 4;
    const float* src;
    float* dst;
    if (i < XN)               { src = X  + i;               dst = g_Xr + i; }
    else if (i < XN + WN)     { src = Wq + (i - XN);        dst = g_Wq + (i - XN); }
    else if (i < XN + 2 * WN) { src = Wk + (i - XN - WN);   dst = g_Wk + (i - XN - WN); }
    else if (i < XN + 3 * WN) { src = Wv + (i - XN - 2*WN); dst = g_Wv + (i - XN - 2*WN); }
    else                      { src = Wo + (i - XN - 3*WN); dst = g_Wo + (i - XN - 3*WN); }
    float4 v = *(const float4*)src;
    v.x = tf32_rna(v.x); v.y = tf32_rna(v.y);
    v.z = tf32_rna(v.z); v.w = tf32_rna(v.w);
    *(float4*)dst = v;
}

// ===========================================================================
// Flash attention, tf32 mma.sync.
// grid (32, 64), 128 threads = 4 warps, TWO CTAs per SM.
// CTA: 64 q rows; warp: 16 q rows. KV blocks of 64, double-buffered cp.async.
// ===========================================================================
#define ARS   68
#define ARB   272
#define KVT_B (64 * ARB)                   // 17408
#define ASMEM (4 * KVT_B + 64 * ARB)       // 87040

__global__ __launch_bounds__(128, 2)
void attn_mma_kernel()
{
    extern __shared__ float sm[];
    float* sP = sm + 4 * 64 * ARS;         // [64][68], also Q staging

    const int tid = threadIdx.x;
    const int w   = tid >> 5;
    const int lane = tid & 31;
    const int qb = blockIdx.x;
    const int bh = blockIdx.y;

    const float* Qp  = g_Q  + (size_t)bh * (Ssz * HDsz) + (size_t)qb * 64 * HDsz;
    const float* Kp  = g_K  + (size_t)bh * (Ssz * HDsz);
    const float* Vtp = g_Vt + (size_t)bh * (HDsz * Ssz);

    const uint32_t sKb = smem_u32(sm);
    const uint32_t sVb = sKb + 2 * KVT_B;
    const uint32_t sPb = sKb + 4 * KVT_B;

    // ---- stage Q (64 rows), build persistent A-fragments ----
#pragma unroll
    for (int i = 0; i < 8; i++) {
        int id = tid + i * 128;            // 0..1023
        int r = id >> 4, ch = id & 15;
        *(float4*)&sP[r * ARS + ch * 4] = *(const float4*)&Qp[r * 64 + ch * 4];
    }
    __syncthreads();

    const int a_row = (lane & 7) + ((lane >> 3) & 1) * 8;
    const int a_co  = (lane >> 4) * 4;
    const int b_row = (lane & 7) + (lane >> 4) * 8;
    const int b_co  = ((lane >> 3) & 1) * 4;

    uint32_t qf[8][4];
#pragma unroll
    for (int kc = 0; kc < 8; kc++)
        ldsm_x4(qf[kc][0], qf[kc][1], qf[kc][2], qf[kc][3],
                sPb + (uint32_t)((w * 16 + a_row) * ARB + (kc * 8 + a_co) * 4));
    __syncthreads();

    auto load_kv = [&](int kb, int buf) {
        const float* kg = Kp  + (size_t)kb * 64 * 64;
        const float* vg = Vtp + kb * 64;
        const uint32_t kd = sKb + buf * KVT_B;
        const uint32_t vd = sVb + buf * KVT_B;
#pragma unroll
        for (int i = 0; i < 8; i++) {
            int id = tid + i * 128;        // 0..1023
            int r = id >> 4, ch = id & 15;
            cp16(kd + r * ARB + ch * 16, kg + r * 64 + ch * 4);
            cp16(vd + r * ARB + ch * 16, vg + (size_t)r * Ssz + ch * 4);
        }
        asm volatile("cp.async.commit_group;" ::: "memory");
    };

    load_kv(0, 0);
    load_kv(1, 1);

    float m[2] = {-1e30f, -1e30f}, l[2] = {0.0f, 0.0f};
    float of[8][4];
#pragma unroll
    for (int nt = 0; nt < 8; nt++)
#pragma unroll
        for (int q = 0; q < 4; q++) of[nt][q] = 0.0f;

    const uint32_t pw = sPb + (uint32_t)(w * 16) * ARB;

    for (int kb = 0; kb < 32; kb++) {
        const int buf = kb & 1;
        // pending groups at top: {kb, kb+1}
        if (kb < 31) asm volatile("cp.async.wait_group 1;" ::: "memory");
        else         asm volatile("cp.async.wait_group 0;" ::: "memory");
        __syncthreads();

        const uint32_t kbase = sKb + buf * KVT_B;
        const uint32_t vbase = sVb + buf * KVT_B;

        // ---- S = Q K^T (log2 domain) ----
        float sc[8][4];
#pragma unroll
        for (int nt = 0; nt < 8; nt++)
#pragma unroll
            for (int q = 0; q < 4; q++) sc[nt][q] = 0.0f;

#pragma unroll
        for (int kc = 0; kc < 8; kc++) {
#pragma unroll
            for (int p = 0; p < 4; p++) {
                uint32_t r0, r1, r2, r3;
                ldsm_x4(r0, r1, r2, r3,
                        kbase + (uint32_t)((p * 16 + b_row) * ARB + (kc * 8 + b_co) * 4));
                uint32_t b0[2] = {r0, r1}, b1[2] = {r2, r3};
                mma_tf32(sc[2 * p],     qf[kc], b0);
                mma_tf32(sc[2 * p + 1], qf[kc], b1);
            }
        }

        // ---- online softmax in exp2 domain ----
        float ml0 = -1e30f, ml1 = -1e30f;
#pragma unroll
        for (int nt = 0; nt < 8; nt++) {
            ml0 = fmaxf(ml0, fmaxf(sc[nt][0], sc[nt][1]));
            ml1 = fmaxf(ml1, fmaxf(sc[nt][2], sc[nt][3]));
        }
        ml0 = fmaxf(ml0, __shfl_xor_sync(0xffffffffu, ml0, 1));
        ml0 = fmaxf(ml0, __shfl_xor_sync(0xffffffffu, ml0, 2));
        ml1 = fmaxf(ml1, __shfl_xor_sync(0xffffffffu, ml1, 1));
        ml1 = fmaxf(ml1, __shfl_xor_sync(0xffffffffu, ml1, 2));

        const float mn0 = fmaxf(m[0], ml0), mn1 = fmaxf(m[1], ml1);
        const float a0 = exp2f(m[0] - mn0), a1 = exp2f(m[1] - mn1);
        m[0] = mn0; m[1] = mn1;

        float ll0 = 0.0f, ll1 = 0.0f;
#pragma unroll
        for (int nt = 0; nt < 8; nt++) {
            sc[nt][0] = exp2f(sc[nt][0] - mn0);
            sc[nt][1] = exp2f(sc[nt][1] - mn0);
            sc[nt][2] = exp2f(sc[nt][2] - mn1);
            sc[nt][3] = exp2f(sc[nt][3] - mn1);
            ll0 += sc[nt][0] + sc[nt][1];
            ll1 += sc[nt][2] + sc[nt][3];
        }
        ll0 += __shfl_xor_sync(0xffffffffu, ll0, 1);
        ll0 += __shfl_xor_sync(0xffffffffu, ll0, 2);
        ll1 += __shfl_xor_sync(0xffffffffu, ll1, 1);
        ll1 += __shfl_xor_sync(0xffffffffu, ll1, 2);
        l[0] = l[0] * a0 + ll0;
        l[1] = l[1] * a1 + ll1;

#pragma unroll
        for (int nt = 0; nt < 8; nt++) {
            of[nt][0] *= a0; of[nt][1] *= a0;
            of[nt][2] *= a1; of[nt][3] *= a1;
        }

        // ---- P -> warp-private smem (RNA), reload as A-fragments ----
        {
            const uint32_t r0a = pw + (uint32_t)((lane >> 2) * ARB + 2 * (lane & 3) * 4);
#pragma unroll
            for (int nt = 0; nt < 8; nt++) {
                float2 v0 = make_float2(tf32_rna(sc[nt][0]), tf32_rna(sc[nt][1]));
                float2 v1 = make_float2(tf32_rna(sc[nt][2]), tf32_rna(sc[nt][3]));
                asm volatile("st.shared.v2.f32 [%0], {%1, %2};"
                             :: "r"(r0a + nt * 32), "f"(v0.x), "f"(v0.y));
                asm volatile("st.shared.v2.f32 [%0], {%1, %2};"
                             :: "r"(r0a + 8 * ARB + nt * 32), "f"(v1.x), "f"(v1.y));
            }
        }
        __syncwarp();

        // ---- O += P V ----
#pragma unroll
        for (int kc = 0; kc < 8; kc++) {
            uint32_t af[4];
            ldsm_x4(af[0], af[1], af[2], af[3],
                    pw + (uint32_t)(a_row * ARB + (kc * 8 + a_co) * 4));
#pragma unroll
            for (int p = 0; p < 4; p++) {
                uint32_t r0, r1, r2, r3;
                ldsm_x4(r0, r1, r2, r3,
                        vbase + (uint32_t)((p * 16 + b_row) * ARB + (kc * 8 + b_co) * 4));
                uint32_t b0[2] = {r0, r1}, b1[2] = {r2, r3};
                mma_tf32(of[2 * p],     af, b0);
                mma_tf32(of[2 * p + 1], af, b1);
            }
        }

        __syncthreads();                   // readers done with buf
        if (kb + 2 < 32) load_kv(kb + 2, buf);
    }

    // ---- epilogue ----
    const float inv0 = 1.0f / l[0], inv1 = 1.0f / l[1];
    const int b = bh >> 4, h = bh & 15;
    const int s0 = qb * 64 + w * 16 + (lane >> 2);
#pragma unroll
    for (int nt = 0; nt < 8; nt++) {
        int n = h * 64 + nt * 8 + 2 * (lane & 3);
        float2 v0, v1;
        v0.x = tf32_rna(of[nt][0] * inv0);
        v0.y = tf32_rna(of[nt][1] * inv0);
        v1.x = tf32_rna(of[nt][2] * inv1);
        v1.y = tf32_rna(of[nt][3] * inv1);
        *(float2*)&g_AO[(size_t)(b * Ssz + s0) * Dsz + n]       = v0;
        *(float2*)&g_AO[(size_t)(b * Ssz + s0 + 8) * Dsz + n]   = v1;
    }
}

// ===========================================================================
extern "C" void kernel_launch(void* const* d_in, const int* in_sizes, int n_in,
                              void* d_out, int out_size)
{
    const float* X  = (const float*)d_in[0];
    const float* Wq = (const float*)d_in[1];
    const float* Wk = (const float*)d_in[2];
    const float* Wv = (const float*)d_in[3];
    const float* Wo = (const float*)d_in[4];
    float* Out = (float*)d_out;

    cudaFuncSetAttribute(qkv_mma_kernel,
                         cudaFuncAttributeMaxDynamicSharedMemorySize, GSMEM);
    cudaFuncSetAttribute(out_mma_kernel,
                         cudaFuncAttributeMaxDynamicSharedMemorySize, GSMEM);
    cudaFuncSetAttribute(attn_mma_kernel,
                         cudaFuncAttributeMaxDynamicSharedMemorySize, ASMEM);

    round_all_kernel<<<(XN + 4 * WN) / 1024, 256>>>(X, Wq, Wk, Wv, Wo);

    dim3 gq(8, 64, 3);
    qkv_mma_kernel<<<gq, 256, GSMEM>>>();

    dim3 ga(32, 64);
    attn_mma_kernel<<<ga, 128, ASMEM>>>();

    dim3 go(8, 64);
    out_mma_kernel<<<go, 256, GSMEM>>>(Out);
}